// round 13
// baseline (speedup 1.0000x reference)
#include <cuda_runtime.h>
#include <cuda_bf16.h>
#include <cuda_fp16.h>
#include <math.h>
#include <stdint.h>

#define N_NODES   100000
#define N_EDGES   3200000
#define D         512
#define N_CLASSES 40
#define NSCAN_BLK 98

// ---------------- scratch (device globals; no allocs allowed) ----------------
__device__ __half g_bufA[(size_t)N_NODES * D];  // node features fp16, canonical layout
__device__ __half g_bufB[(size_t)N_NODES * D];
__device__ __half g_z16[(size_t)N_NODES * D];   // GEMM out / SpMM in, canonical
__device__ __half g_z40[(size_t)N_NODES * N_CLASSES];
__device__ __half g_wl[D * D];                   // W^T [n][k] fp16 canonical
__device__ __half g_w0[D * D];
__device__ __half g_w1[D * D];
__device__ __half g_w2[128 * D];                 // W2^T [n][k], padded to 128 rows
__device__ int   g_indeg[N_NODES];
__device__ int   g_outdeg[N_NODES];
__device__ float g_norm_src[N_NODES];
__device__ float g_norm_dst[N_NODES];
__device__ int   g_rowptr[N_NODES + 1];
__device__ int   g_rowctr[N_NODES];
__device__ int   g_csr_src[N_EDGES];
__device__ int   g_blksum[NSCAN_BLK];
__device__ int   g_blkoff[NSCAN_BLK];

// ---------------- helpers ----------------
__device__ __forceinline__ void cp16(uint32_t dst_smem, const void* src, bool valid) {
    asm volatile("cp.async.cg.shared.global [%0], [%1], 16, %2;"
                 :: "r"(dst_smem), "l"(src), "r"(valid ? 16 : 0));
}
__device__ __forceinline__ void cp_commit() {
    asm volatile("cp.async.commit_group;");
}
template <int N>
__device__ __forceinline__ void cp_wait() {
    asm volatile("cp.async.wait_group %0;" :: "n"(N));
}

#define LDM4(r, addr)                                                          \
    asm volatile("ldmatrix.sync.aligned.m8n8.x4.shared.b16 {%0,%1,%2,%3}, [%4];" \
                 : "=r"((r)[0]), "=r"((r)[1]), "=r"((r)[2]), "=r"((r)[3])      \
                 : "r"(addr))

#define MMA_F16(c, a0, a1, a2, a3, b0, b1)                                     \
    asm volatile("mma.sync.aligned.m16n8k16.row.col.f32.f16.f16.f32 "          \
                 "{%0,%1,%2,%3}, {%4,%5,%6,%7}, {%8,%9}, {%0,%1,%2,%3};"       \
                 : "+f"(c[0]), "+f"(c[1]), "+f"(c[2]), "+f"(c[3])              \
                 : "r"(a0), "r"(a1), "r"(a2), "r"(a3), "r"(b0), "r"(b1))

// ---------------- conversion passes (canonical layouts) ----------------
__global__ void k_conv_feat(const float* __restrict__ f) {
    size_t i = ((size_t)blockIdx.x * blockDim.x + threadIdx.x) * 8;
    float4 a = *(const float4*)(f + i);
    float4 b = *(const float4*)(f + i + 4);
    __half2 h0 = __floats2half2_rn(a.x, a.y);
    __half2 h1 = __floats2half2_rn(a.z, a.w);
    __half2 h2 = __floats2half2_rn(b.x, b.y);
    __half2 h3 = __floats2half2_rn(b.z, b.w);
    *(uint4*)(g_bufA + i) = make_uint4(*(uint32_t*)&h0, *(uint32_t*)&h1,
                                       *(uint32_t*)&h2, *(uint32_t*)&h3);
}

// W [k][n] fp32 -> W^T [n][k] fp16
__global__ void k_conv_w(const float* __restrict__ W, __half* __restrict__ Wt) {
    int idx = blockIdx.x * blockDim.x + threadIdx.x;
    int k = idx >> 9, n = idx & 511;
    Wt[n * 512 + k] = __float2half(W[k * 512 + n]);
}

// W2 [k][40] -> padded [n][k], n 0..127
__global__ void k_conv_w2(const float* __restrict__ W2) {
    int idx = blockIdx.x * blockDim.x + threadIdx.x;   // 128*512
    int n = idx >> 9, k = idx & 511;
    float v = (n < N_CLASSES) ? W2[k * N_CLASSES + n] : 0.f;
    g_w2[n * 512 + k] = __float2half(v);
}

// ---------------- graph preprocessing ----------------
__global__ void k_zero_ints() {
    int i = blockIdx.x * blockDim.x + threadIdx.x;
    if (i < N_NODES) { g_indeg[i] = 0; g_outdeg[i] = 0; g_rowctr[i] = 0; }
}

__global__ void k_degrees(const int* __restrict__ src, const int* __restrict__ dst) {
    int e = blockIdx.x * blockDim.x + threadIdx.x;
    if (e < N_EDGES) {
        atomicAdd(&g_outdeg[src[e]], 1);
        atomicAdd(&g_indeg[dst[e]], 1);
    }
}

__global__ void k_norms() {
    int i = blockIdx.x * blockDim.x + threadIdx.x;
    if (i < N_NODES) {
        g_norm_src[i] = rsqrtf(fmaxf((float)g_outdeg[i], 1.0f));
        g_norm_dst[i] = rsqrtf(fmaxf((float)g_indeg[i], 1.0f));
    }
}

__global__ void k_scan1() {
    __shared__ int ws[32];
    int tid = threadIdx.x, lane = tid & 31, w = tid >> 5;
    int i = blockIdx.x * 1024 + tid;
    int v = (i < N_NODES) ? g_indeg[i] : 0;
    int x = v;
    #pragma unroll
    for (int o = 1; o < 32; o <<= 1) {
        int y = __shfl_up_sync(0xFFFFFFFFu, x, o);
        if (lane >= o) x += y;
    }
    if (lane == 31) ws[w] = x;
    __syncthreads();
    if (w == 0) {
        int y = ws[lane];
        #pragma unroll
        for (int o = 1; o < 32; o <<= 1) {
            int z = __shfl_up_sync(0xFFFFFFFFu, y, o);
            if (lane >= o) y += z;
        }
        ws[lane] = y;
    }
    __syncthreads();
    int incl = x + (w > 0 ? ws[w - 1] : 0);
    if (i < N_NODES) g_rowptr[i + 1] = incl;
    if (tid == 1023) g_blksum[blockIdx.x] = incl;
}

__global__ void k_scan2() {
    __shared__ int ws[4];
    int tid = threadIdx.x, lane = tid & 31, w = tid >> 5;
    int v = (tid < NSCAN_BLK) ? g_blksum[tid] : 0;
    int x = v;
    #pragma unroll
    for (int o = 1; o < 32; o <<= 1) {
        int y = __shfl_up_sync(0xFFFFFFFFu, x, o);
        if (lane >= o) x += y;
    }
    if (lane == 31) ws[w] = x;
    __syncthreads();
    if (tid == 0) {
        int s = 0;
        #pragma unroll
        for (int j = 0; j < 4; j++) { int t = ws[j]; ws[j] = s; s += t; }
    }
    __syncthreads();
    int excl = x - v + ws[w];
    if (tid < NSCAN_BLK) g_blkoff[tid] = excl;
}

__global__ void k_scan3() {
    int i = blockIdx.x * 1024 + threadIdx.x;
    if (i < N_NODES) g_rowptr[i + 1] += g_blkoff[blockIdx.x];
    if (i == 0) g_rowptr[0] = 0;
}

__global__ void k_scatter(const int* __restrict__ src, const int* __restrict__ dst) {
    int e = blockIdx.x * blockDim.x + threadIdx.x;
    if (e < N_EDGES) {
        int d = dst[e];
        int pos = g_rowptr[d] + atomicAdd(&g_rowctr[d], 1);
        g_csr_src[pos] = src[e];
    }
}

// ---------------- fp16 tensor-core GEMM (ldmatrix, k64 stages, 1 barrier/stage) ----------------
// MODE 0: C = acc + bias     -> fp16 Ch
// MODE 1: C = acc * scale[r] -> fp16 C16
// MODE 2: C = acc * scale[r] -> fp16 C40, row stride 40, cols < 40 only
// stage: A 128 rows x 144B (128B content) + B same. 3 stages = 110592 B.
#define ROWB   144
#define PARTB  (128 * ROWB)        // 18432
#define STGB   (2 * PARTB)         // 36864
#define SMEM_G (3 * STGB)          // 110592

template <int MODE>
__global__ __launch_bounds__(256, 2) void k_gemm_tc(
        const __half* __restrict__ A, const __half* __restrict__ B,
        const float* __restrict__ bias, const float* __restrict__ row_scale,
        __half* __restrict__ Ch, __half* __restrict__ C16,
        __half* __restrict__ C40, int M, int col_base) {
    extern __shared__ char smc[];
    uint32_t sbase = (uint32_t)__cvta_generic_to_shared(smc);

    int tid  = threadIdx.x;
    int lane = tid & 31;
    int warp = tid >> 5;
    int wm = (warp & 3) * 32;
    int wn = (warp >> 2) * 64;
    int row0 = blockIdx.y * 128;
    int col0 = (blockIdx.x + col_base) * 128;

    float acc[2][8][4];
    #pragma unroll
    for (int i = 0; i < 2; i++)
        #pragma unroll
        for (int j = 0; j < 8; j++)
            #pragma unroll
            for (int k = 0; k < 4; k++) acc[i][j][k] = 0.f;

    // cp.async: thread -> row (tid>>1), 64B half-row (tid&1); 4 chunks of 16B each
    const int r_ld = tid >> 1;
    const int half = tid & 1;
    const bool a_ok = (row0 + r_ld) < M;
    const size_t a_off = (size_t)(row0 + r_ld) * D + half * 32;   // halves
    const size_t b_off = (size_t)(col0 + r_ld) * D + half * 32;
    const uint32_t dstA = (uint32_t)r_ld * ROWB + half * 64;      // bytes

    auto issue = [&](int st, int ks) {
        int k0 = ks * 64;                                         // halves
        uint32_t sb = sbase + st * STGB;
        const char* pa = (const char*)(A + a_off + k0);
        const char* pb = (const char*)(B + b_off + k0);
        #pragma unroll
        for (int j = 0; j < 4; j++) {
            cp16(sb + dstA + j * 16,         pa + j * 16, a_ok);
            cp16(sb + PARTB + dstA + j * 16, pb + j * 16, true);
        }
        cp_commit();
    };

    issue(0, 0);
    issue(1, 1);

    // ldmatrix per-lane offsets (bytes, relative to stage base)
    const uint32_t a_lane = (uint32_t)(wm + (lane & 7) + ((lane >> 3) & 1) * 8) * ROWB
                          + ((lane >> 4) & 1) * 16;
    const uint32_t b_lane = PARTB
                          + (uint32_t)(wn + (lane & 7) + ((lane >> 4) & 1) * 8) * ROWB
                          + ((lane >> 3) & 1) * 16;

    const int NK = D / 64;   // 8
    for (int ks = 0; ks < NK; ks++) {
        if (ks < NK - 1) cp_wait<1>(); else cp_wait<0>();
        __syncthreads();                       // single barrier per stage
        if (ks + 2 < NK) issue((ks + 2) % 3, ks + 2);

        uint32_t sb = sbase + (ks % 3) * STGB;
        #pragma unroll
        for (int sub = 0; sub < 4; sub++) {    // 4 k16 sub-slices per k64 stage
            uint32_t a0[4], a1[4];
            LDM4(a0, sb + a_lane + sub * 32);
            LDM4(a1, sb + a_lane + 16 * ROWB + sub * 32);
            #pragma unroll
            for (int ntp = 0; ntp < 4; ntp++) {
                uint32_t bq[4];
                LDM4(bq, sb + b_lane + ntp * 16 * ROWB + sub * 32);
                MMA_F16(acc[0][2 * ntp],     a0[0], a0[1], a0[2], a0[3], bq[0], bq[1]);
                MMA_F16(acc[1][2 * ntp],     a1[0], a1[1], a1[2], a1[3], bq[0], bq[1]);
                MMA_F16(acc[0][2 * ntp + 1], a0[0], a0[1], a0[2], a0[3], bq[2], bq[3]);
                MMA_F16(acc[1][2 * ntp + 1], a1[0], a1[1], a1[2], a1[3], bq[2], bq[3]);
            }
        }
    }

    int fr = lane >> 2;
    int fc = (lane & 3) * 2;
    #pragma unroll
    for (int mt = 0; mt < 2; mt++) {
        int r = row0 + wm + mt * 16 + fr;
        float s0 = 1.f, s1 = 1.f;
        if (MODE != 0) {
            if (r < M)     s0 = row_scale[r];
            if (r + 8 < M) s1 = row_scale[r + 8];
        }
        #pragma unroll
        for (int nt = 0; nt < 8; nt++) {
            int cb = col0 + wn + nt * 8 + fc;
            float v0 = acc[mt][nt][0], v1 = acc[mt][nt][1];
            float v2 = acc[mt][nt][2], v3 = acc[mt][nt][3];
            if (MODE == 0) {
                float bb0 = bias[cb], bb1 = bias[cb + 1];
                __half2 h01 = __floats2half2_rn(v0 + bb0, v1 + bb1);
                __half2 h23 = __floats2half2_rn(v2 + bb0, v3 + bb1);
                if (r < M)     *(__half2*)(Ch + (size_t)r * D + cb)       = h01;
                if (r + 8 < M) *(__half2*)(Ch + (size_t)(r + 8) * D + cb) = h23;
            } else if (MODE == 1) {
                if (r < M)
                    *(__half2*)(C16 + (size_t)r * D + cb) = __floats2half2_rn(v0 * s0, v1 * s0);
                if (r + 8 < M)
                    *(__half2*)(C16 + (size_t)(r + 8) * D + cb) = __floats2half2_rn(v2 * s1, v3 * s1);
            } else {
                if (cb < N_CLASSES) {
                    if (r < M)
                        *(__half2*)(C40 + (size_t)r * N_CLASSES + cb) = __floats2half2_rn(v0 * s0, v1 * s0);
                    if (r + 8 < M)
                        *(__half2*)(C40 + (size_t)(r + 8) * N_CLASSES + cb) = __floats2half2_rn(v2 * s1, v3 * s1);
                }
            }
        }
    }
}

// ---------------- SpMM: fp16 gather, 2 x 256-col chunks; writes fp16 h ----------------
__global__ __launch_bounds__(128) void k_spmm16(const __half* __restrict__ z,
                                                const float* __restrict__ bias,
                                                __half* __restrict__ O,
                                                int chunk) {
    int v = blockIdx.x * 4 + (threadIdx.x >> 5);
    if (v >= N_NODES) return;
    int lane = threadIdx.x & 31;
    int coff = chunk * 256 + lane * 8;

    int beg = g_rowptr[v], end = g_rowptr[v + 1];
    float acc[8];
    #pragma unroll
    for (int j = 0; j < 8; j++) acc[j] = 0.f;

    int e = beg;
    for (; e + 3 < end; e += 4) {
        int u0 = g_csr_src[e];
        int u1 = g_csr_src[e + 1];
        int u2 = g_csr_src[e + 2];
        int u3 = g_csr_src[e + 3];
        uint4 q0 = *(const uint4*)(z + (size_t)u0 * D + coff);
        uint4 q1 = *(const uint4*)(z + (size_t)u1 * D + coff);
        uint4 q2 = *(const uint4*)(z + (size_t)u2 * D + coff);
        uint4 q3 = *(const uint4*)(z + (size_t)u3 * D + coff);
        const __half2* p0 = (const __half2*)&q0;
        const __half2* p1 = (const __half2*)&q1;
        const __half2* p2 = (const __half2*)&q2;
        const __half2* p3 = (const __half2*)&q3;
        #pragma unroll
        for (int p = 0; p < 4; p++) {
            float2 f0 = __half22float2(p0[p]);
            float2 f1 = __half22float2(p1[p]);
            float2 f2 = __half22float2(p2[p]);
            float2 f3 = __half22float2(p3[p]);
            acc[2 * p]     += (f0.x + f1.x) + (f2.x + f3.x);
            acc[2 * p + 1] += (f0.y + f1.y) + (f2.y + f3.y);
        }
    }
    for (; e < end; e++) {
        int u0 = g_csr_src[e];
        uint4 q0 = *(const uint4*)(z + (size_t)u0 * D + coff);
        const __half2* p0 = (const __half2*)&q0;
        #pragma unroll
        for (int p = 0; p < 4; p++) {
            float2 f0 = __half22float2(p0[p]);
            acc[2 * p]     += f0.x;
            acc[2 * p + 1] += f0.y;
        }
    }

    float nd = g_norm_dst[v];
    float4 b0v = *(const float4*)(bias + coff);
    float4 b1v = *(const float4*)(bias + coff + 4);
    float bb[8] = { b0v.x, b0v.y, b0v.z, b0v.w, b1v.x, b1v.y, b1v.z, b1v.w };
    __half2 oh[4];
    #pragma unroll
    for (int p = 0; p < 4; p++) {
        float x = fmaxf(fmaf(acc[2 * p],     nd, bb[2 * p]),     0.f);
        float y = fmaxf(fmaf(acc[2 * p + 1], nd, bb[2 * p + 1]), 0.f);
        oh[p] = __floats2half2_rn(x, y);
    }
    *(uint4*)(O + (size_t)v * D + coff) =
        make_uint4(*(uint32_t*)&oh[0], *(uint32_t*)&oh[1],
                   *(uint32_t*)&oh[2], *(uint32_t*)&oh[3]);
}

// ---------------- final SpMM on 40-wide fp16 z40 (L2-resident) ----------------
__global__ __launch_bounds__(256) void k_spmm40(const __half* __restrict__ z40,
                                                const float* __restrict__ bias,
                                                float* __restrict__ out) {
    int v = blockIdx.x * 8 + (threadIdx.x >> 5);
    if (v >= N_NODES) return;
    int lane = threadIdx.x & 31;
    if (lane >= 20) return;
    int c = lane * 2;

    int beg = g_rowptr[v], end = g_rowptr[v + 1];
    float2 acc0 = make_float2(0.f, 0.f);
    float2 acc1 = make_float2(0.f, 0.f);
    int e = beg;
    for (; e + 1 < end; e += 2) {
        int u0 = g_csr_src[e];
        int u1 = g_csr_src[e + 1];
        __half2 x0 = *(const __half2*)(z40 + (size_t)u0 * N_CLASSES + c);
        __half2 x1 = *(const __half2*)(z40 + (size_t)u1 * N_CLASSES + c);
        float2 f0 = __half22float2(x0);
        float2 f1 = __half22float2(x1);
        acc0.x += f0.x; acc0.y += f0.y;
        acc1.x += f1.x; acc1.y += f1.y;
    }
    if (e < end) {
        int u0 = g_csr_src[e];
        __half2 x0 = *(const __half2*)(z40 + (size_t)u0 * N_CLASSES + c);
        float2 f0 = __half22float2(x0);
        acc0.x += f0.x; acc0.y += f0.y;
    }
    float nd = g_norm_dst[v];
    float2 o;
    o.x = fmaf(acc0.x + acc1.x, nd, bias[c]);
    o.y = fmaf(acc0.y + acc1.y, nd, bias[c + 1]);
    *(float2*)(out + (size_t)v * N_CLASSES + c) = o;
}

// ---------------- launch ----------------
extern "C" void kernel_launch(void* const* d_in, const int* in_sizes, int n_in,
                              void* d_out, int out_size) {
    const float* features = (const float*)d_in[0];
    const int*   src      = (const int*)d_in[1];
    const int*   dst      = (const int*)d_in[2];
    const float* W_lin    = (const float*)d_in[3];
    const float* b_lin    = (const float*)d_in[4];
    const float* W0       = (const float*)d_in[5];
    const float* b0       = (const float*)d_in[6];
    const float* W1       = (const float*)d_in[7];
    const float* b1       = (const float*)d_in[8];
    const float* W2       = (const float*)d_in[9];
    const float* b2       = (const float*)d_in[10];
    float* out = (float*)d_out;

    static cudaStream_t s1 = nullptr, s2 = nullptr;
    static cudaEvent_t evFork, evW, evGraph, evA0, evC0, evA1, evC1;
    if (s1 == nullptr) {
        cudaStreamCreateWithFlags(&s1, cudaStreamNonBlocking);
        cudaStreamCreateWithFlags(&s2, cudaStreamNonBlocking);
        cudaEventCreateWithFlags(&evFork,  cudaEventDisableTiming);
        cudaEventCreateWithFlags(&evW,     cudaEventDisableTiming);
        cudaEventCreateWithFlags(&evGraph, cudaEventDisableTiming);
        cudaEventCreateWithFlags(&evA0,    cudaEventDisableTiming);
        cudaEventCreateWithFlags(&evC0,    cudaEventDisableTiming);
        cudaEventCreateWithFlags(&evA1,    cudaEventDisableTiming);
        cudaEventCreateWithFlags(&evC1,    cudaEventDisableTiming);
        cudaFuncSetAttribute(k_gemm_tc<0>, cudaFuncAttributeMaxDynamicSharedMemorySize, SMEM_G);
        cudaFuncSetAttribute(k_gemm_tc<1>, cudaFuncAttributeMaxDynamicSharedMemorySize, SMEM_G);
        cudaFuncSetAttribute(k_gemm_tc<2>, cudaFuncAttributeMaxDynamicSharedMemorySize, SMEM_G);
    }

    __half *bufA, *bufB, *wl, *w0, *w1, *w2, *z16, *z40;
    float *ns;
    cudaGetSymbolAddress((void**)&bufA, g_bufA);
    cudaGetSymbolAddress((void**)&bufB, g_bufB);
    cudaGetSymbolAddress((void**)&wl, g_wl);
    cudaGetSymbolAddress((void**)&w0, g_w0);
    cudaGetSymbolAddress((void**)&w1, g_w1);
    cudaGetSymbolAddress((void**)&w2, g_w2);
    cudaGetSymbolAddress((void**)&z16, g_z16);
    cudaGetSymbolAddress((void**)&z40, g_z40);
    cudaGetSymbolAddress((void**)&ns, g_norm_src);

    const int NB_N = (N_NODES + 255) / 256;
    const int NB_E = (N_EDGES + 255) / 256;
    dim3 gfull(4, (N_NODES + 127) / 128);
    dim3 ghalf(2, (N_NODES + 127) / 128);
    dim3 g40(1, (N_NODES + 127) / 128);
    const int spmm_blocks = (N_NODES + 3) / 4;

    cudaEventRecord(evFork, 0);
    cudaStreamWaitEvent(s1, evFork, 0);

    // main-stream prep first, so GEMM0 is global launch index 3 for ncu
    k_conv_feat<<<(int)(((size_t)N_NODES * D / 8) / 256), 256>>>(features);    // 0
    k_conv_w<<<1024, 256>>>(W_lin, wl);                                        // 1
    k_conv_w<<<1024, 256, 0, s1>>>(W0, w0);                                    // 2
    k_gemm_tc<0><<<gfull, 256, SMEM_G>>>(bufA, wl, b_lin, nullptr,             // 3 <- profiled
                                         bufB, nullptr, nullptr, N_NODES, 0);
    // side stream: remaining weights + graph build; evW AFTER norms
    k_conv_w<<<1024, 256, 0, s1>>>(W1, w1);
    k_conv_w2<<<256, 256, 0, s1>>>(W2);
    k_zero_ints<<<NB_N, 256, 0, s1>>>();
    k_degrees<<<NB_E, 256, 0, s1>>>(src, dst);
    k_norms<<<NB_N, 256, 0, s1>>>();
    cudaEventRecord(evW, s1);
    k_scan1<<<NSCAN_BLK, 1024, 0, s1>>>();
    k_scan2<<<1, 128, 0, s1>>>();
    k_scan3<<<NSCAN_BLK, 1024, 0, s1>>>();
    k_scatter<<<NB_E, 256, 0, s1>>>(src, dst);
    cudaEventRecord(evGraph, s1);

    cudaStreamWaitEvent(0, evW, 0);

    // layer 0: column-split GEMM; SpMM chunk0 overlapped on s2
    k_gemm_tc<1><<<ghalf, 256, SMEM_G>>>(bufB, w0, nullptr, ns,
                                         nullptr, z16, nullptr, N_NODES, 0);
    cudaEventRecord(evA0, 0);
    k_gemm_tc<1><<<ghalf, 256, SMEM_G>>>(bufB, w0, nullptr, ns,
                                         nullptr, z16, nullptr, N_NODES, 2);
    cudaStreamWaitEvent(0, evGraph, 0);
    cudaStreamWaitEvent(s2, evGraph, 0);
    cudaStreamWaitEvent(s2, evA0, 0);
    k_spmm16<<<spmm_blocks, 128, 0, s2>>>(z16, b0, bufA, 0);
    cudaEventRecord(evC0, s2);
    k_spmm16<<<spmm_blocks, 128>>>(z16, b0, bufA, 1);
    cudaStreamWaitEvent(0, evC0, 0);

    // layer 1
    k_gemm_tc<1><<<ghalf, 256, SMEM_G>>>(bufA, w1, nullptr, ns,
                                         nullptr, z16, nullptr, N_NODES, 0);
    cudaEventRecord(evA1, 0);
    k_gemm_tc<1><<<ghalf, 256, SMEM_G>>>(bufA, w1, nullptr, ns,
                                         nullptr, z16, nullptr, N_NODES, 2);
    cudaStreamWaitEvent(s2, evA1, 0);
    k_spmm16<<<spmm_blocks, 128, 0, s2>>>(z16, b1, bufB, 0);
    cudaEventRecord(evC1, s2);
    k_spmm16<<<spmm_blocks, 128>>>(z16, b1, bufB, 1);
    cudaStreamWaitEvent(0, evC1, 0);

    // layer 2
    k_gemm_tc<2><<<g40, 256, SMEM_G>>>(bufB, w2, nullptr, ns,
                                       nullptr, nullptr, z40, N_NODES, 0);
    k_spmm40<<<(N_NODES + 7) / 8, 256>>>(z40, b2, out);
}

// round 14
// speedup vs baseline: 1.1227x; 1.1227x over previous
#include <cuda_runtime.h>
#include <cuda_bf16.h>
#include <cuda_fp16.h>
#include <math.h>
#include <stdint.h>

#define N_NODES   100000
#define N_EDGES   3200000
#define D         512
#define N_CLASSES 40
#define NSCAN_BLK 98

// ---------------- scratch (device globals; no allocs allowed) ----------------
__device__ __half g_bufA[(size_t)N_NODES * D];  // node features fp16, canonical layout
__device__ __half g_bufB[(size_t)N_NODES * D];
__device__ __half g_z16[(size_t)N_NODES * D];   // GEMM out / SpMM in, canonical
__device__ __half g_z40[(size_t)N_NODES * N_CLASSES];
__device__ __half g_wl[D * D];                   // W^T [n][k] fp16 canonical
__device__ __half g_w0[D * D];
__device__ __half g_w1[D * D];
__device__ __half g_w2[128 * D];                 // W2^T [n][k], padded to 128 rows
__device__ int   g_indeg[N_NODES];
__device__ int   g_outdeg[N_NODES];
__device__ float g_norm_src[N_NODES];
__device__ float g_norm_dst[N_NODES];
__device__ int   g_rowptr[N_NODES + 1];
__device__ int   g_rowctr[N_NODES];
__device__ int   g_csr_src[N_EDGES];
__device__ int   g_blksum[NSCAN_BLK];
__device__ int   g_blkoff[NSCAN_BLK];

// ---------------- helpers ----------------
__device__ __forceinline__ void cp16(uint32_t dst_smem, const void* src, bool valid) {
    asm volatile("cp.async.cg.shared.global [%0], [%1], 16, %2;"
                 :: "r"(dst_smem), "l"(src), "r"(valid ? 16 : 0));
}
__device__ __forceinline__ void cp_commit() {
    asm volatile("cp.async.commit_group;");
}
template <int N>
__device__ __forceinline__ void cp_wait() {
    asm volatile("cp.async.wait_group %0;" :: "n"(N));
}

#define LDM4(r, addr)                                                          \
    asm volatile("ldmatrix.sync.aligned.m8n8.x4.shared.b16 {%0,%1,%2,%3}, [%4];" \
                 : "=r"((r)[0]), "=r"((r)[1]), "=r"((r)[2]), "=r"((r)[3])      \
                 : "r"(addr))

#define MMA_F16(c, a0, a1, a2, a3, b0, b1)                                     \
    asm volatile("mma.sync.aligned.m16n8k16.row.col.f32.f16.f16.f32 "          \
                 "{%0,%1,%2,%3}, {%4,%5,%6,%7}, {%8,%9}, {%0,%1,%2,%3};"       \
                 : "+f"(c[0]), "+f"(c[1]), "+f"(c[2]), "+f"(c[3])              \
                 : "r"(a0), "r"(a1), "r"(a2), "r"(a3), "r"(b0), "r"(b1))

// ---------------- conversion passes (canonical layouts) ----------------
__global__ void k_conv_feat(const float* __restrict__ f) {
    size_t i = ((size_t)blockIdx.x * blockDim.x + threadIdx.x) * 8;
    float4 a = *(const float4*)(f + i);
    float4 b = *(const float4*)(f + i + 4);
    __half2 h0 = __floats2half2_rn(a.x, a.y);
    __half2 h1 = __floats2half2_rn(a.z, a.w);
    __half2 h2 = __floats2half2_rn(b.x, b.y);
    __half2 h3 = __floats2half2_rn(b.z, b.w);
    *(uint4*)(g_bufA + i) = make_uint4(*(uint32_t*)&h0, *(uint32_t*)&h1,
                                       *(uint32_t*)&h2, *(uint32_t*)&h3);
}

// W [k][n] fp32 -> W^T [n][k] fp16
__global__ void k_conv_w(const float* __restrict__ W, __half* __restrict__ Wt) {
    int idx = blockIdx.x * blockDim.x + threadIdx.x;
    int k = idx >> 9, n = idx & 511;
    Wt[n * 512 + k] = __float2half(W[k * 512 + n]);
}

// W2 [k][40] -> padded [n][k], n 0..127
__global__ void k_conv_w2(const float* __restrict__ W2) {
    int idx = blockIdx.x * blockDim.x + threadIdx.x;   // 128*512
    int n = idx >> 9, k = idx & 511;
    float v = (n < N_CLASSES) ? W2[k * N_CLASSES + n] : 0.f;
    g_w2[n * 512 + k] = __float2half(v);
}

// ---------------- graph preprocessing ----------------
__global__ void k_zero_ints() {
    int i = blockIdx.x * blockDim.x + threadIdx.x;
    if (i < N_NODES) { g_indeg[i] = 0; g_outdeg[i] = 0; g_rowctr[i] = 0; }
}

__global__ void k_degrees(const int* __restrict__ src, const int* __restrict__ dst) {
    int e = blockIdx.x * blockDim.x + threadIdx.x;
    if (e < N_EDGES) {
        atomicAdd(&g_outdeg[src[e]], 1);
        atomicAdd(&g_indeg[dst[e]], 1);
    }
}

__global__ void k_norms() {
    int i = blockIdx.x * blockDim.x + threadIdx.x;
    if (i < N_NODES) {
        g_norm_src[i] = rsqrtf(fmaxf((float)g_outdeg[i], 1.0f));
        g_norm_dst[i] = rsqrtf(fmaxf((float)g_indeg[i], 1.0f));
    }
}

__global__ void k_scan1() {
    __shared__ int ws[32];
    int tid = threadIdx.x, lane = tid & 31, w = tid >> 5;
    int i = blockIdx.x * 1024 + tid;
    int v = (i < N_NODES) ? g_indeg[i] : 0;
    int x = v;
    #pragma unroll
    for (int o = 1; o < 32; o <<= 1) {
        int y = __shfl_up_sync(0xFFFFFFFFu, x, o);
        if (lane >= o) x += y;
    }
    if (lane == 31) ws[w] = x;
    __syncthreads();
    if (w == 0) {
        int y = ws[lane];
        #pragma unroll
        for (int o = 1; o < 32; o <<= 1) {
            int z = __shfl_up_sync(0xFFFFFFFFu, y, o);
            if (lane >= o) y += z;
        }
        ws[lane] = y;
    }
    __syncthreads();
    int incl = x + (w > 0 ? ws[w - 1] : 0);
    if (i < N_NODES) g_rowptr[i + 1] = incl;
    if (tid == 1023) g_blksum[blockIdx.x] = incl;
}

__global__ void k_scan2() {
    __shared__ int ws[4];
    int tid = threadIdx.x, lane = tid & 31, w = tid >> 5;
    int v = (tid < NSCAN_BLK) ? g_blksum[tid] : 0;
    int x = v;
    #pragma unroll
    for (int o = 1; o < 32; o <<= 1) {
        int y = __shfl_up_sync(0xFFFFFFFFu, x, o);
        if (lane >= o) x += y;
    }
    if (lane == 31) ws[w] = x;
    __syncthreads();
    if (tid == 0) {
        int s = 0;
        #pragma unroll
        for (int j = 0; j < 4; j++) { int t = ws[j]; ws[j] = s; s += t; }
    }
    __syncthreads();
    int excl = x - v + ws[w];
    if (tid < NSCAN_BLK) g_blkoff[tid] = excl;
}

__global__ void k_scan3() {
    int i = blockIdx.x * 1024 + threadIdx.x;
    if (i < N_NODES) g_rowptr[i + 1] += g_blkoff[blockIdx.x];
    if (i == 0) g_rowptr[0] = 0;
}

__global__ void k_scatter(const int* __restrict__ src, const int* __restrict__ dst) {
    int e = blockIdx.x * blockDim.x + threadIdx.x;
    if (e < N_EDGES) {
        int d = dst[e];
        int pos = g_rowptr[d] + atomicAdd(&g_rowctr[d], 1);
        g_csr_src[pos] = src[e];
    }
}

// ---------------- fp16 tensor-core GEMM (ldmatrix, k32 stages x4, 1 barrier/stage) ----------------
// MODE 0: C = acc + bias     -> fp16 Ch
// MODE 1: C = acc * scale[r] -> fp16 C16
// MODE 2: C = acc * scale[r] -> fp16 C40, row stride 40, cols < 40 only
// stage: A 128 rows x 80B + B same (64B content + 16B pad). 4 stages = 81920 B.
#define ROWB   80
#define PARTB  (128 * ROWB)        // 10240
#define STGB   (2 * PARTB)         // 20480
#define NSTG   4
#define SMEM_G (NSTG * STGB)       // 81920

template <int MODE>
__global__ __launch_bounds__(256, 2) void k_gemm_tc(
        const __half* __restrict__ A, const __half* __restrict__ B,
        const float* __restrict__ bias, const float* __restrict__ row_scale,
        __half* __restrict__ Ch, __half* __restrict__ C16,
        __half* __restrict__ C40, int M, int col_base) {
    extern __shared__ char smc[];
    uint32_t sbase = (uint32_t)__cvta_generic_to_shared(smc);

    int tid  = threadIdx.x;
    int lane = tid & 31;
    int warp = tid >> 5;
    int wm = (warp & 3) * 32;
    int wn = (warp >> 2) * 64;
    int row0 = blockIdx.y * 128;
    int col0 = (blockIdx.x + col_base) * 128;

    float acc[2][8][4];
    #pragma unroll
    for (int i = 0; i < 2; i++)
        #pragma unroll
        for (int j = 0; j < 8; j++)
            #pragma unroll
            for (int k = 0; k < 4; k++) acc[i][j][k] = 0.f;

    // cp.async: thread -> row (tid>>1), 16-half half-row (tid&1)
    const int r_ld = tid >> 1;
    const int half = tid & 1;
    const bool a_ok = (row0 + r_ld) < M;
    const size_t a_off = (size_t)(row0 + r_ld) * D + half * 16;   // halves
    const size_t b_off = (size_t)(col0 + r_ld) * D + half * 16;
    const uint32_t dstA = (uint32_t)r_ld * ROWB + half * 32;      // bytes

    auto issue = [&](int st, int ks) {
        int k0 = ks * 32;
        uint32_t sb = sbase + st * STGB;
        const char* pa = (const char*)(A + a_off + k0);
        const char* pb = (const char*)(B + b_off + k0);
        cp16(sb + dstA,               pa,      a_ok);
        cp16(sb + dstA + 16,          pa + 16, a_ok);
        cp16(sb + PARTB + dstA,       pb,      true);
        cp16(sb + PARTB + dstA + 16,  pb + 16, true);
        cp_commit();
    };

    issue(0, 0);
    issue(1, 1);
    issue(2, 2);

    // ldmatrix per-lane address offsets (relative to stage base, bytes)
    const uint32_t a_lane = (uint32_t)(wm + (lane & 7) + ((lane >> 3) & 1) * 8) * ROWB
                          + ((lane >> 4) & 1) * 16;
    const uint32_t b_lane = PARTB
                          + (uint32_t)(wn + (lane & 7) + ((lane >> 4) & 1) * 8) * ROWB
                          + ((lane >> 3) & 1) * 16;

    const int NK = D / 32;   // 16
    for (int ks = 0; ks < NK; ks++) {
        if (ks < NK - 2) cp_wait<2>();
        else if (ks < NK - 1) cp_wait<1>();
        else cp_wait<0>();
        __syncthreads();                           // single barrier per stage
        if (ks + 3 < NK) issue((ks + 3) % NSTG, ks + 3);

        uint32_t sb = sbase + (ks % NSTG) * STGB;
        #pragma unroll
        for (int sub = 0; sub < 2; sub++) {
            uint32_t a0[4], a1[4];
            LDM4(a0, sb + a_lane + sub * 32);
            LDM4(a1, sb + a_lane + 16 * ROWB + sub * 32);
            #pragma unroll
            for (int ntp = 0; ntp < 4; ntp++) {
                uint32_t bq[4];
                LDM4(bq, sb + b_lane + ntp * 16 * ROWB + sub * 32);
                MMA_F16(acc[0][2 * ntp],     a0[0], a0[1], a0[2], a0[3], bq[0], bq[1]);
                MMA_F16(acc[1][2 * ntp],     a1[0], a1[1], a1[2], a1[3], bq[0], bq[1]);
                MMA_F16(acc[0][2 * ntp + 1], a0[0], a0[1], a0[2], a0[3], bq[2], bq[3]);
                MMA_F16(acc[1][2 * ntp + 1], a1[0], a1[1], a1[2], a1[3], bq[2], bq[3]);
            }
        }
    }

    int fr = lane >> 2;
    int fc = (lane & 3) * 2;
    #pragma unroll
    for (int mt = 0; mt < 2; mt++) {
        int r = row0 + wm + mt * 16 + fr;
        float s0 = 1.f, s1 = 1.f;
        if (MODE != 0) {
            if (r < M)     s0 = row_scale[r];
            if (r + 8 < M) s1 = row_scale[r + 8];
        }
        #pragma unroll
        for (int nt = 0; nt < 8; nt++) {
            int cb = col0 + wn + nt * 8 + fc;
            float v0 = acc[mt][nt][0], v1 = acc[mt][nt][1];
            float v2 = acc[mt][nt][2], v3 = acc[mt][nt][3];
            if (MODE == 0) {
                float bb0 = bias[cb], bb1 = bias[cb + 1];
                __half2 h01 = __floats2half2_rn(v0 + bb0, v1 + bb1);
                __half2 h23 = __floats2half2_rn(v2 + bb0, v3 + bb1);
                if (r < M)     *(__half2*)(Ch + (size_t)r * D + cb)       = h01;
                if (r + 8 < M) *(__half2*)(Ch + (size_t)(r + 8) * D + cb) = h23;
            } else if (MODE == 1) {
                if (r < M)
                    *(__half2*)(C16 + (size_t)r * D + cb) = __floats2half2_rn(v0 * s0, v1 * s0);
                if (r + 8 < M)
                    *(__half2*)(C16 + (size_t)(r + 8) * D + cb) = __floats2half2_rn(v2 * s1, v3 * s1);
            } else {
                if (cb < N_CLASSES) {
                    if (r < M)
                        *(__half2*)(C40 + (size_t)r * N_CLASSES + cb) = __floats2half2_rn(v0 * s0, v1 * s0);
                    if (r + 8 < M)
                        *(__half2*)(C40 + (size_t)(r + 8) * N_CLASSES + cb) = __floats2half2_rn(v2 * s1, v3 * s1);
                }
            }
        }
    }
}

// ---------------- SpMM: fp16 gather, 2 x 256-col chunks; writes fp16 h ----------------
__global__ __launch_bounds__(128) void k_spmm16(const __half* __restrict__ z,
                                                const float* __restrict__ bias,
                                                __half* __restrict__ O,
                                                int chunk) {
    int v = blockIdx.x * 4 + (threadIdx.x >> 5);
    if (v >= N_NODES) return;
    int lane = threadIdx.x & 31;
    int coff = chunk * 256 + lane * 8;

    int beg = g_rowptr[v], end = g_rowptr[v + 1];
    float acc[8];
    #pragma unroll
    for (int j = 0; j < 8; j++) acc[j] = 0.f;

    int e = beg;
    for (; e + 3 < end; e += 4) {
        int u0 = g_csr_src[e];
        int u1 = g_csr_src[e + 1];
        int u2 = g_csr_src[e + 2];
        int u3 = g_csr_src[e + 3];
        uint4 q0 = *(const uint4*)(z + (size_t)u0 * D + coff);
        uint4 q1 = *(const uint4*)(z + (size_t)u1 * D + coff);
        uint4 q2 = *(const uint4*)(z + (size_t)u2 * D + coff);
        uint4 q3 = *(const uint4*)(z + (size_t)u3 * D + coff);
        const __half2* p0 = (const __half2*)&q0;
        const __half2* p1 = (const __half2*)&q1;
        const __half2* p2 = (const __half2*)&q2;
        const __half2* p3 = (const __half2*)&q3;
        #pragma unroll
        for (int p = 0; p < 4; p++) {
            float2 f0 = __half22float2(p0[p]);
            float2 f1 = __half22float2(p1[p]);
            float2 f2 = __half22float2(p2[p]);
            float2 f3 = __half22float2(p3[p]);
            acc[2 * p]     += (f0.x + f1.x) + (f2.x + f3.x);
            acc[2 * p + 1] += (f0.y + f1.y) + (f2.y + f3.y);
        }
    }
    for (; e < end; e++) {
        int u0 = g_csr_src[e];
        uint4 q0 = *(const uint4*)(z + (size_t)u0 * D + coff);
        const __half2* p0 = (const __half2*)&q0;
        #pragma unroll
        for (int p = 0; p < 4; p++) {
            float2 f0 = __half22float2(p0[p]);
            acc[2 * p]     += f0.x;
            acc[2 * p + 1] += f0.y;
        }
    }

    float nd = g_norm_dst[v];
    float4 b0v = *(const float4*)(bias + coff);
    float4 b1v = *(const float4*)(bias + coff + 4);
    float bb[8] = { b0v.x, b0v.y, b0v.z, b0v.w, b1v.x, b1v.y, b1v.z, b1v.w };
    __half2 oh[4];
    #pragma unroll
    for (int p = 0; p < 4; p++) {
        float x = fmaxf(fmaf(acc[2 * p],     nd, bb[2 * p]),     0.f);
        float y = fmaxf(fmaf(acc[2 * p + 1], nd, bb[2 * p + 1]), 0.f);
        oh[p] = __floats2half2_rn(x, y);
    }
    *(uint4*)(O + (size_t)v * D + coff) =
        make_uint4(*(uint32_t*)&oh[0], *(uint32_t*)&oh[1],
                   *(uint32_t*)&oh[2], *(uint32_t*)&oh[3]);
}

// ---------------- final SpMM on 40-wide fp16 z40 (L2-resident) ----------------
__global__ __launch_bounds__(256) void k_spmm40(const __half* __restrict__ z40,
                                                const float* __restrict__ bias,
                                                float* __restrict__ out) {
    int v = blockIdx.x * 8 + (threadIdx.x >> 5);
    if (v >= N_NODES) return;
    int lane = threadIdx.x & 31;
    if (lane >= 20) return;
    int c = lane * 2;

    int beg = g_rowptr[v], end = g_rowptr[v + 1];
    float2 acc0 = make_float2(0.f, 0.f);
    float2 acc1 = make_float2(0.f, 0.f);
    int e = beg;
    for (; e + 1 < end; e += 2) {
        int u0 = g_csr_src[e];
        int u1 = g_csr_src[e + 1];
        __half2 x0 = *(const __half2*)(z40 + (size_t)u0 * N_CLASSES + c);
        __half2 x1 = *(const __half2*)(z40 + (size_t)u1 * N_CLASSES + c);
        float2 f0 = __half22float2(x0);
        float2 f1 = __half22float2(x1);
        acc0.x += f0.x; acc0.y += f0.y;
        acc1.x += f1.x; acc1.y += f1.y;
    }
    if (e < end) {
        int u0 = g_csr_src[e];
        __half2 x0 = *(const __half2*)(z40 + (size_t)u0 * N_CLASSES + c);
        float2 f0 = __half22float2(x0);
        acc0.x += f0.x; acc0.y += f0.y;
    }
    float nd = g_norm_dst[v];
    float2 o;
    o.x = fmaf(acc0.x + acc1.x, nd, bias[c]);
    o.y = fmaf(acc0.y + acc1.y, nd, bias[c + 1]);
    *(float2*)(out + (size_t)v * N_CLASSES + c) = o;
}

// ---------------- launch ----------------
extern "C" void kernel_launch(void* const* d_in, const int* in_sizes, int n_in,
                              void* d_out, int out_size) {
    const float* features = (const float*)d_in[0];
    const int*   src      = (const int*)d_in[1];
    const int*   dst      = (const int*)d_in[2];
    const float* W_lin    = (const float*)d_in[3];
    const float* b_lin    = (const float*)d_in[4];
    const float* W0       = (const float*)d_in[5];
    const float* b0       = (const float*)d_in[6];
    const float* W1       = (const float*)d_in[7];
    const float* b1       = (const float*)d_in[8];
    const float* W2       = (const float*)d_in[9];
    const float* b2       = (const float*)d_in[10];
    float* out = (float*)d_out;

    static cudaStream_t s1 = nullptr, s2 = nullptr;
    static cudaEvent_t evFork, evW, evGraph, evA0, evC0, evA1, evC1;
    if (s1 == nullptr) {
        cudaStreamCreateWithFlags(&s1, cudaStreamNonBlocking);
        cudaStreamCreateWithFlags(&s2, cudaStreamNonBlocking);
        cudaEventCreateWithFlags(&evFork,  cudaEventDisableTiming);
        cudaEventCreateWithFlags(&evW,     cudaEventDisableTiming);
        cudaEventCreateWithFlags(&evGraph, cudaEventDisableTiming);
        cudaEventCreateWithFlags(&evA0,    cudaEventDisableTiming);
        cudaEventCreateWithFlags(&evC0,    cudaEventDisableTiming);
        cudaEventCreateWithFlags(&evA1,    cudaEventDisableTiming);
        cudaEventCreateWithFlags(&evC1,    cudaEventDisableTiming);
        cudaFuncSetAttribute(k_gemm_tc<0>, cudaFuncAttributeMaxDynamicSharedMemorySize, SMEM_G);
        cudaFuncSetAttribute(k_gemm_tc<1>, cudaFuncAttributeMaxDynamicSharedMemorySize, SMEM_G);
        cudaFuncSetAttribute(k_gemm_tc<2>, cudaFuncAttributeMaxDynamicSharedMemorySize, SMEM_G);
    }

    __half *bufA, *bufB, *wl, *w0, *w1, *w2, *z16, *z40;
    float *ns;
    cudaGetSymbolAddress((void**)&bufA, g_bufA);
    cudaGetSymbolAddress((void**)&bufB, g_bufB);
    cudaGetSymbolAddress((void**)&wl, g_wl);
    cudaGetSymbolAddress((void**)&w0, g_w0);
    cudaGetSymbolAddress((void**)&w1, g_w1);
    cudaGetSymbolAddress((void**)&w2, g_w2);
    cudaGetSymbolAddress((void**)&z16, g_z16);
    cudaGetSymbolAddress((void**)&z40, g_z40);
    cudaGetSymbolAddress((void**)&ns, g_norm_src);

    const int NB_N = (N_NODES + 255) / 256;
    const int NB_E = (N_EDGES + 255) / 256;
    dim3 gfull(4, (N_NODES + 127) / 128);
    dim3 ghalf(2, (N_NODES + 127) / 128);
    dim3 g40(1, (N_NODES + 127) / 128);
    const int spmm_blocks = (N_NODES + 3) / 4;

    cudaEventRecord(evFork, 0);
    cudaStreamWaitEvent(s1, evFork, 0);

    // main-stream prep first, so GEMM0 is global launch index 3 for ncu
    k_conv_feat<<<(int)(((size_t)N_NODES * D / 8) / 256), 256>>>(features);    // 0
    k_conv_w<<<1024, 256>>>(W_lin, wl);                                        // 1
    k_conv_w<<<1024, 256, 0, s1>>>(W0, w0);                                    // 2
    k_gemm_tc<0><<<gfull, 256, SMEM_G>>>(bufA, wl, b_lin, nullptr,             // 3 <- profiled
                                         bufB, nullptr, nullptr, N_NODES, 0);
    // side stream: remaining weights + graph build; evW AFTER norms
    k_conv_w<<<1024, 256, 0, s1>>>(W1, w1);
    k_conv_w2<<<256, 256, 0, s1>>>(W2);
    k_zero_ints<<<NB_N, 256, 0, s1>>>();
    k_degrees<<<NB_E, 256, 0, s1>>>(src, dst);
    k_norms<<<NB_N, 256, 0, s1>>>();
    cudaEventRecord(evW, s1);
    k_scan1<<<NSCAN_BLK, 1024, 0, s1>>>();
    k_scan2<<<1, 128, 0, s1>>>();
    k_scan3<<<NSCAN_BLK, 1024, 0, s1>>>();
    k_scatter<<<NB_E, 256, 0, s1>>>(src, dst);
    cudaEventRecord(evGraph, s1);

    cudaStreamWaitEvent(0, evW, 0);

    // layer 0: column-split GEMM; SpMM chunk0 overlapped on s2
    k_gemm_tc<1><<<ghalf, 256, SMEM_G>>>(bufB, w0, nullptr, ns,
                                         nullptr, z16, nullptr, N_NODES, 0);
    cudaEventRecord(evA0, 0);
    k_gemm_tc<1><<<ghalf, 256, SMEM_G>>>(bufB, w0, nullptr, ns,
                                         nullptr, z16, nullptr, N_NODES, 2);
    cudaStreamWaitEvent(0, evGraph, 0);
    cudaStreamWaitEvent(s2, evGraph, 0);
    cudaStreamWaitEvent(s2, evA0, 0);
    k_spmm16<<<spmm_blocks, 128, 0, s2>>>(z16, b0, bufA, 0);
    cudaEventRecord(evC0, s2);
    k_spmm16<<<spmm_blocks, 128>>>(z16, b0, bufA, 1);
    cudaStreamWaitEvent(0, evC0, 0);

    // layer 1
    k_gemm_tc<1><<<ghalf, 256, SMEM_G>>>(bufA, w1, nullptr, ns,
                                         nullptr, z16, nullptr, N_NODES, 0);
    cudaEventRecord(evA1, 0);
    k_gemm_tc<1><<<ghalf, 256, SMEM_G>>>(bufA, w1, nullptr, ns,
                                         nullptr, z16, nullptr, N_NODES, 2);
    cudaStreamWaitEvent(s2, evA1, 0);
    k_spmm16<<<spmm_blocks, 128, 0, s2>>>(z16, b1, bufB, 0);
    cudaEventRecord(evC1, s2);
    k_spmm16<<<spmm_blocks, 128>>>(z16, b1, bufB, 1);
    cudaStreamWaitEvent(0, evC1, 0);

    // layer 2
    k_gemm_tc<2><<<g40, 256, SMEM_G>>>(bufB, w2, nullptr, ns,
                                       nullptr, nullptr, z40, N_NODES, 0);
    k_spmm40<<<(N_NODES + 7) / 8, 256>>>(z40, b2, out);
}

// round 15
// speedup vs baseline: 1.1940x; 1.0635x over previous
#include <cuda_runtime.h>
#include <cuda_bf16.h>
#include <cuda_fp16.h>
#include <math.h>
#include <stdint.h>

#define N_NODES   100000
#define N_EDGES   3200000
#define D         512
#define N_CLASSES 40
#define NSCAN_BLK 98

// ---------------- scratch (device globals; no allocs allowed) ----------------
__device__ __half g_bufA[(size_t)N_NODES * D];  // node features fp16, canonical layout
__device__ __half g_bufB[(size_t)N_NODES * D];
__device__ __half g_z16[(size_t)N_NODES * D];   // GEMM out / SpMM in, canonical
__device__ __half g_z40[(size_t)N_NODES * N_CLASSES];
__device__ __half g_wl[D * D];                   // W^T [n][k] fp16 canonical
__device__ __half g_w0[D * D];
__device__ __half g_w1[D * D];
__device__ __half g_w2[128 * D];                 // W2^T [n][k], padded to 128 rows
__device__ int   g_indeg[N_NODES];
__device__ int   g_outdeg[N_NODES];
__device__ float g_norm_src[N_NODES];
__device__ float g_norm_dst[N_NODES];
__device__ int   g_rowptr[N_NODES + 1];
__device__ int   g_rowctr[N_NODES];
__device__ int   g_csr_src[N_EDGES];
__device__ int   g_blksum[NSCAN_BLK];
__device__ int   g_blkoff[NSCAN_BLK];

// ---------------- helpers ----------------
__device__ __forceinline__ void cp16(uint32_t dst_smem, const void* src, bool valid) {
    asm volatile("cp.async.cg.shared.global [%0], [%1], 16, %2;"
                 :: "r"(dst_smem), "l"(src), "r"(valid ? 16 : 0));
}
__device__ __forceinline__ void cp_commit() {
    asm volatile("cp.async.commit_group;");
}
template <int N>
__device__ __forceinline__ void cp_wait() {
    asm volatile("cp.async.wait_group %0;" :: "n"(N));
}

#define LDM4(r, addr)                                                          \
    asm volatile("ldmatrix.sync.aligned.m8n8.x4.shared.b16 {%0,%1,%2,%3}, [%4];" \
                 : "=r"((r)[0]), "=r"((r)[1]), "=r"((r)[2]), "=r"((r)[3])      \
                 : "r"(addr))

#define MMA_F16(c, a0, a1, a2, a3, b0, b1)                                     \
    asm volatile("mma.sync.aligned.m16n8k16.row.col.f32.f16.f16.f32 "          \
                 "{%0,%1,%2,%3}, {%4,%5,%6,%7}, {%8,%9}, {%0,%1,%2,%3};"       \
                 : "+f"(c[0]), "+f"(c[1]), "+f"(c[2]), "+f"(c[3])              \
                 : "r"(a0), "r"(a1), "r"(a2), "r"(a3), "r"(b0), "r"(b1))

// ---------------- conversion passes (canonical layouts) ----------------
__global__ void k_conv_feat(const float* __restrict__ f) {
    size_t i = ((size_t)blockIdx.x * blockDim.x + threadIdx.x) * 8;
    float4 a = *(const float4*)(f + i);
    float4 b = *(const float4*)(f + i + 4);
    __half2 h0 = __floats2half2_rn(a.x, a.y);
    __half2 h1 = __floats2half2_rn(a.z, a.w);
    __half2 h2 = __floats2half2_rn(b.x, b.y);
    __half2 h3 = __floats2half2_rn(b.z, b.w);
    *(uint4*)(g_bufA + i) = make_uint4(*(uint32_t*)&h0, *(uint32_t*)&h1,
                                       *(uint32_t*)&h2, *(uint32_t*)&h3);
}

// W [k][n] fp32 -> W^T [n][k] fp16
__global__ void k_conv_w(const float* __restrict__ W, __half* __restrict__ Wt) {
    int idx = blockIdx.x * blockDim.x + threadIdx.x;
    int k = idx >> 9, n = idx & 511;
    Wt[n * 512 + k] = __float2half(W[k * 512 + n]);
}

// W2 [k][40] -> padded [n][k], n 0..127
__global__ void k_conv_w2(const float* __restrict__ W2) {
    int idx = blockIdx.x * blockDim.x + threadIdx.x;   // 128*512
    int n = idx >> 9, k = idx & 511;
    float v = (n < N_CLASSES) ? W2[k * N_CLASSES + n] : 0.f;
    g_w2[n * 512 + k] = __float2half(v);
}

// ---------------- graph preprocessing ----------------
__global__ void k_zero_ints() {
    int i = blockIdx.x * blockDim.x + threadIdx.x;
    if (i < N_NODES) { g_indeg[i] = 0; g_outdeg[i] = 0; g_rowctr[i] = 0; }
}

__global__ void k_degrees(const int* __restrict__ src, const int* __restrict__ dst) {
    int e = blockIdx.x * blockDim.x + threadIdx.x;
    if (e < N_EDGES) {
        atomicAdd(&g_outdeg[src[e]], 1);
        atomicAdd(&g_indeg[dst[e]], 1);
    }
}

__global__ void k_norms() {
    int i = blockIdx.x * blockDim.x + threadIdx.x;
    if (i < N_NODES) {
        g_norm_src[i] = rsqrtf(fmaxf((float)g_outdeg[i], 1.0f));
        g_norm_dst[i] = rsqrtf(fmaxf((float)g_indeg[i], 1.0f));
    }
}

__global__ void k_scan1() {
    __shared__ int ws[32];
    int tid = threadIdx.x, lane = tid & 31, w = tid >> 5;
    int i = blockIdx.x * 1024 + tid;
    int v = (i < N_NODES) ? g_indeg[i] : 0;
    int x = v;
    #pragma unroll
    for (int o = 1; o < 32; o <<= 1) {
        int y = __shfl_up_sync(0xFFFFFFFFu, x, o);
        if (lane >= o) x += y;
    }
    if (lane == 31) ws[w] = x;
    __syncthreads();
    if (w == 0) {
        int y = ws[lane];
        #pragma unroll
        for (int o = 1; o < 32; o <<= 1) {
            int z = __shfl_up_sync(0xFFFFFFFFu, y, o);
            if (lane >= o) y += z;
        }
        ws[lane] = y;
    }
    __syncthreads();
    int incl = x + (w > 0 ? ws[w - 1] : 0);
    if (i < N_NODES) g_rowptr[i + 1] = incl;
    if (tid == 1023) g_blksum[blockIdx.x] = incl;
}

__global__ void k_scan2() {
    __shared__ int ws[4];
    int tid = threadIdx.x, lane = tid & 31, w = tid >> 5;
    int v = (tid < NSCAN_BLK) ? g_blksum[tid] : 0;
    int x = v;
    #pragma unroll
    for (int o = 1; o < 32; o <<= 1) {
        int y = __shfl_up_sync(0xFFFFFFFFu, x, o);
        if (lane >= o) x += y;
    }
    if (lane == 31) ws[w] = x;
    __syncthreads();
    if (tid == 0) {
        int s = 0;
        #pragma unroll
        for (int j = 0; j < 4; j++) { int t = ws[j]; ws[j] = s; s += t; }
    }
    __syncthreads();
    int excl = x - v + ws[w];
    if (tid < NSCAN_BLK) g_blkoff[tid] = excl;
}

__global__ void k_scan3() {
    int i = blockIdx.x * 1024 + threadIdx.x;
    if (i < N_NODES) g_rowptr[i + 1] += g_blkoff[blockIdx.x];
    if (i == 0) g_rowptr[0] = 0;
}

__global__ void k_scatter(const int* __restrict__ src, const int* __restrict__ dst) {
    int e = blockIdx.x * blockDim.x + threadIdx.x;
    if (e < N_EDGES) {
        int d = dst[e];
        int pos = g_rowptr[d] + atomicAdd(&g_rowctr[d], 1);
        g_csr_src[pos] = src[e];
    }
}

// ---------------- fp16 tensor-core GEMM (ldmatrix; R12 config: 3 stages, 2 barriers) ----------------
// MODE 0: C = acc + bias     -> fp16 Ch
// MODE 1: C = acc * scale[r] -> fp16 C16
// MODE 2: C = acc * scale[r] -> fp16 C40, row stride 40, cols < 40 only
#define ROWB   80
#define PARTB  (128 * ROWB)        // 10240
#define STGB   (2 * PARTB)         // 20480
#define SMEM_G (3 * STGB)          // 61440

template <int MODE>
__global__ __launch_bounds__(256, 2) void k_gemm_tc(
        const __half* __restrict__ A, const __half* __restrict__ B,
        const float* __restrict__ bias, const float* __restrict__ row_scale,
        __half* __restrict__ Ch, __half* __restrict__ C16,
        __half* __restrict__ C40, int M, int col_base) {
    extern __shared__ char smc[];
    uint32_t sbase = (uint32_t)__cvta_generic_to_shared(smc);

    int tid  = threadIdx.x;
    int lane = tid & 31;
    int warp = tid >> 5;
    int wm = (warp & 3) * 32;
    int wn = (warp >> 2) * 64;
    int row0 = blockIdx.y * 128;
    int col0 = (blockIdx.x + col_base) * 128;

    float acc[2][8][4];
    #pragma unroll
    for (int i = 0; i < 2; i++)
        #pragma unroll
        for (int j = 0; j < 8; j++)
            #pragma unroll
            for (int k = 0; k < 4; k++) acc[i][j][k] = 0.f;

    // cp.async: thread -> row (tid>>1), 16-half half-row (tid&1)
    const int r_ld = tid >> 1;
    const int half = tid & 1;
    const bool a_ok = (row0 + r_ld) < M;
    const size_t a_off = (size_t)(row0 + r_ld) * D + half * 16;   // halves
    const size_t b_off = (size_t)(col0 + r_ld) * D + half * 16;
    const uint32_t dstA = (uint32_t)r_ld * ROWB + half * 32;      // bytes

    auto issue = [&](int st, int ks) {
        int k0 = ks * 32;
        uint32_t sb = sbase + st * STGB;
        const char* pa = (const char*)(A + a_off + k0);
        const char* pb = (const char*)(B + b_off + k0);
        cp16(sb + dstA,               pa,      a_ok);
        cp16(sb + dstA + 16,          pa + 16, a_ok);
        cp16(sb + PARTB + dstA,       pb,      true);
        cp16(sb + PARTB + dstA + 16,  pb + 16, true);
        cp_commit();
    };

    issue(0, 0);
    issue(1, 1);

    // ldmatrix per-lane address offsets (relative to stage base, bytes)
    const uint32_t a_lane = (uint32_t)(wm + (lane & 7) + ((lane >> 3) & 1) * 8) * ROWB
                          + ((lane >> 4) & 1) * 16;
    const uint32_t b_lane = PARTB
                          + (uint32_t)(wn + (lane & 7) + ((lane >> 4) & 1) * 8) * ROWB
                          + ((lane >> 3) & 1) * 16;

    const int NK = D / 32;   // 16
    for (int ks = 0; ks < NK; ks++) {
        if (ks < NK - 1) cp_wait<1>(); else cp_wait<0>();
        __syncthreads();
        if (ks + 2 < NK) issue((ks + 2) % 3, ks + 2);

        uint32_t sb = sbase + (ks % 3) * STGB;
        #pragma unroll
        for (int sub = 0; sub < 2; sub++) {
            uint32_t a0[4], a1[4];
            LDM4(a0, sb + a_lane + sub * 32);
            LDM4(a1, sb + a_lane + 16 * ROWB + sub * 32);
            #pragma unroll
            for (int ntp = 0; ntp < 4; ntp++) {
                uint32_t bq[4];
                LDM4(bq, sb + b_lane + ntp * 16 * ROWB + sub * 32);
                MMA_F16(acc[0][2 * ntp],     a0[0], a0[1], a0[2], a0[3], bq[0], bq[1]);
                MMA_F16(acc[1][2 * ntp],     a1[0], a1[1], a1[2], a1[3], bq[0], bq[1]);
                MMA_F16(acc[0][2 * ntp + 1], a0[0], a0[1], a0[2], a0[3], bq[2], bq[3]);
                MMA_F16(acc[1][2 * ntp + 1], a1[0], a1[1], a1[2], a1[3], bq[2], bq[3]);
            }
        }
        __syncthreads();
    }

    int fr = lane >> 2;
    int fc = (lane & 3) * 2;
    #pragma unroll
    for (int mt = 0; mt < 2; mt++) {
        int r = row0 + wm + mt * 16 + fr;
        float s0 = 1.f, s1 = 1.f;
        if (MODE != 0) {
            if (r < M)     s0 = row_scale[r];
            if (r + 8 < M) s1 = row_scale[r + 8];
        }
        #pragma unroll
        for (int nt = 0; nt < 8; nt++) {
            int cb = col0 + wn + nt * 8 + fc;
            float v0 = acc[mt][nt][0], v1 = acc[mt][nt][1];
            float v2 = acc[mt][nt][2], v3 = acc[mt][nt][3];
            if (MODE == 0) {
                float bb0 = bias[cb], bb1 = bias[cb + 1];
                __half2 h01 = __floats2half2_rn(v0 + bb0, v1 + bb1);
                __half2 h23 = __floats2half2_rn(v2 + bb0, v3 + bb1);
                if (r < M)     *(__half2*)(Ch + (size_t)r * D + cb)       = h01;
                if (r + 8 < M) *(__half2*)(Ch + (size_t)(r + 8) * D + cb) = h23;
            } else if (MODE == 1) {
                if (r < M)
                    *(__half2*)(C16 + (size_t)r * D + cb) = __floats2half2_rn(v0 * s0, v1 * s0);
                if (r + 8 < M)
                    *(__half2*)(C16 + (size_t)(r + 8) * D + cb) = __floats2half2_rn(v2 * s1, v3 * s1);
            } else {
                if (cb < N_CLASSES) {
                    if (r < M)
                        *(__half2*)(C40 + (size_t)r * N_CLASSES + cb) = __floats2half2_rn(v0 * s0, v1 * s0);
                    if (r + 8 < M)
                        *(__half2*)(C40 + (size_t)(r + 8) * N_CLASSES + cb) = __floats2half2_rn(v2 * s1, v3 * s1);
                }
            }
        }
    }
}

// ---------------- SpMM: fp16 gather, 2 x 256-col chunks; writes fp16 h ----------------
__global__ __launch_bounds__(128) void k_spmm16(const __half* __restrict__ z,
                                                const float* __restrict__ bias,
                                                __half* __restrict__ O,
                                                int chunk) {
    int v = blockIdx.x * 4 + (threadIdx.x >> 5);
    if (v >= N_NODES) return;
    int lane = threadIdx.x & 31;
    int coff = chunk * 256 + lane * 8;

    int beg = g_rowptr[v], end = g_rowptr[v + 1];
    float acc[8];
    #pragma unroll
    for (int j = 0; j < 8; j++) acc[j] = 0.f;

    int e = beg;
    for (; e + 3 < end; e += 4) {
        int u0 = g_csr_src[e];
        int u1 = g_csr_src[e + 1];
        int u2 = g_csr_src[e + 2];
        int u3 = g_csr_src[e + 3];
        uint4 q0 = *(const uint4*)(z + (size_t)u0 * D + coff);
        uint4 q1 = *(const uint4*)(z + (size_t)u1 * D + coff);
        uint4 q2 = *(const uint4*)(z + (size_t)u2 * D + coff);
        uint4 q3 = *(const uint4*)(z + (size_t)u3 * D + coff);
        const __half2* p0 = (const __half2*)&q0;
        const __half2* p1 = (const __half2*)&q1;
        const __half2* p2 = (const __half2*)&q2;
        const __half2* p3 = (const __half2*)&q3;
        #pragma unroll
        for (int p = 0; p < 4; p++) {
            float2 f0 = __half22float2(p0[p]);
            float2 f1 = __half22float2(p1[p]);
            float2 f2 = __half22float2(p2[p]);
            float2 f3 = __half22float2(p3[p]);
            acc[2 * p]     += (f0.x + f1.x) + (f2.x + f3.x);
            acc[2 * p + 1] += (f0.y + f1.y) + (f2.y + f3.y);
        }
    }
    for (; e < end; e++) {
        int u0 = g_csr_src[e];
        uint4 q0 = *(const uint4*)(z + (size_t)u0 * D + coff);
        const __half2* p0 = (const __half2*)&q0;
        #pragma unroll
        for (int p = 0; p < 4; p++) {
            float2 f0 = __half22float2(p0[p]);
            acc[2 * p]     += f0.x;
            acc[2 * p + 1] += f0.y;
        }
    }

    float nd = g_norm_dst[v];
    float4 b0v = *(const float4*)(bias + coff);
    float4 b1v = *(const float4*)(bias + coff + 4);
    float bb[8] = { b0v.x, b0v.y, b0v.z, b0v.w, b1v.x, b1v.y, b1v.z, b1v.w };
    __half2 oh[4];
    #pragma unroll
    for (int p = 0; p < 4; p++) {
        float x = fmaxf(fmaf(acc[2 * p],     nd, bb[2 * p]),     0.f);
        float y = fmaxf(fmaf(acc[2 * p + 1], nd, bb[2 * p + 1]), 0.f);
        oh[p] = __floats2half2_rn(x, y);
    }
    *(uint4*)(O + (size_t)v * D + coff) =
        make_uint4(*(uint32_t*)&oh[0], *(uint32_t*)&oh[1],
                   *(uint32_t*)&oh[2], *(uint32_t*)&oh[3]);
}

// ---------------- final SpMM on 40-wide fp16 z40 (L2-resident) ----------------
__global__ __launch_bounds__(256) void k_spmm40(const __half* __restrict__ z40,
                                                const float* __restrict__ bias,
                                                float* __restrict__ out) {
    int v = blockIdx.x * 8 + (threadIdx.x >> 5);
    if (v >= N_NODES) return;
    int lane = threadIdx.x & 31;
    if (lane >= 20) return;
    int c = lane * 2;

    int beg = g_rowptr[v], end = g_rowptr[v + 1];
    float2 acc0 = make_float2(0.f, 0.f);
    float2 acc1 = make_float2(0.f, 0.f);
    int e = beg;
    for (; e + 1 < end; e += 2) {
        int u0 = g_csr_src[e];
        int u1 = g_csr_src[e + 1];
        __half2 x0 = *(const __half2*)(z40 + (size_t)u0 * N_CLASSES + c);
        __half2 x1 = *(const __half2*)(z40 + (size_t)u1 * N_CLASSES + c);
        float2 f0 = __half22float2(x0);
        float2 f1 = __half22float2(x1);
        acc0.x += f0.x; acc0.y += f0.y;
        acc1.x += f1.x; acc1.y += f1.y;
    }
    if (e < end) {
        int u0 = g_csr_src[e];
        __half2 x0 = *(const __half2*)(z40 + (size_t)u0 * N_CLASSES + c);
        float2 f0 = __half22float2(x0);
        acc0.x += f0.x; acc0.y += f0.y;
    }
    float nd = g_norm_dst[v];
    float2 o;
    o.x = fmaf(acc0.x + acc1.x, nd, bias[c]);
    o.y = fmaf(acc0.y + acc1.y, nd, bias[c + 1]);
    *(float2*)(out + (size_t)v * N_CLASSES + c) = o;
}

// ---------------- launch ----------------
extern "C" void kernel_launch(void* const* d_in, const int* in_sizes, int n_in,
                              void* d_out, int out_size) {
    const float* features = (const float*)d_in[0];
    const int*   src      = (const int*)d_in[1];
    const int*   dst      = (const int*)d_in[2];
    const float* W_lin    = (const float*)d_in[3];
    const float* b_lin    = (const float*)d_in[4];
    const float* W0       = (const float*)d_in[5];
    const float* b0       = (const float*)d_in[6];
    const float* W1       = (const float*)d_in[7];
    const float* b1       = (const float*)d_in[8];
    const float* W2       = (const float*)d_in[9];
    const float* b2       = (const float*)d_in[10];
    float* out = (float*)d_out;

    static cudaStream_t s1 = nullptr, s2 = nullptr;
    static cudaEvent_t evFork, evW, evGraph, evA0, evC0, evA1, evC1;
    if (s1 == nullptr) {
        cudaStreamCreateWithFlags(&s1, cudaStreamNonBlocking);
        cudaStreamCreateWithFlags(&s2, cudaStreamNonBlocking);
        cudaEventCreateWithFlags(&evFork,  cudaEventDisableTiming);
        cudaEventCreateWithFlags(&evW,     cudaEventDisableTiming);
        cudaEventCreateWithFlags(&evGraph, cudaEventDisableTiming);
        cudaEventCreateWithFlags(&evA0,    cudaEventDisableTiming);
        cudaEventCreateWithFlags(&evC0,    cudaEventDisableTiming);
        cudaEventCreateWithFlags(&evA1,    cudaEventDisableTiming);
        cudaEventCreateWithFlags(&evC1,    cudaEventDisableTiming);
        cudaFuncSetAttribute(k_gemm_tc<0>, cudaFuncAttributeMaxDynamicSharedMemorySize, SMEM_G);
        cudaFuncSetAttribute(k_gemm_tc<1>, cudaFuncAttributeMaxDynamicSharedMemorySize, SMEM_G);
        cudaFuncSetAttribute(k_gemm_tc<2>, cudaFuncAttributeMaxDynamicSharedMemorySize, SMEM_G);
    }

    __half *bufA, *bufB, *wl, *w0, *w1, *w2, *z16, *z40;
    float *ns;
    cudaGetSymbolAddress((void**)&bufA, g_bufA);
    cudaGetSymbolAddress((void**)&bufB, g_bufB);
    cudaGetSymbolAddress((void**)&wl, g_wl);
    cudaGetSymbolAddress((void**)&w0, g_w0);
    cudaGetSymbolAddress((void**)&w1, g_w1);
    cudaGetSymbolAddress((void**)&w2, g_w2);
    cudaGetSymbolAddress((void**)&z16, g_z16);
    cudaGetSymbolAddress((void**)&z40, g_z40);
    cudaGetSymbolAddress((void**)&ns, g_norm_src);

    const int NB_N = (N_NODES + 255) / 256;
    const int NB_E = (N_EDGES + 255) / 256;
    dim3 gfull(4, (N_NODES + 127) / 128);
    dim3 ghalf(2, (N_NODES + 127) / 128);
    dim3 g40(1, (N_NODES + 127) / 128);
    const int spmm_blocks = (N_NODES + 3) / 4;

    cudaEventRecord(evFork, 0);
    cudaStreamWaitEvent(s1, evFork, 0);

    // main-stream prep first, so GEMM0 is global launch index 3 for ncu
    k_conv_feat<<<(int)(((size_t)N_NODES * D / 8) / 256), 256>>>(features);    // 0
    k_conv_w<<<1024, 256>>>(W_lin, wl);                                        // 1
    k_conv_w<<<1024, 256, 0, s1>>>(W0, w0);                                    // 2
    k_gemm_tc<0><<<gfull, 256, SMEM_G>>>(bufA, wl, b_lin, nullptr,             // 3 <- profiled
                                         bufB, nullptr, nullptr, N_NODES, 0);
    // side stream: remaining weights + graph build; evW AFTER norms
    k_conv_w<<<1024, 256, 0, s1>>>(W1, w1);
    k_conv_w2<<<256, 256, 0, s1>>>(W2);
    k_zero_ints<<<NB_N, 256, 0, s1>>>();
    k_degrees<<<NB_E, 256, 0, s1>>>(src, dst);
    k_norms<<<NB_N, 256, 0, s1>>>();
    cudaEventRecord(evW, s1);
    k_scan1<<<NSCAN_BLK, 1024, 0, s1>>>();
    k_scan2<<<1, 128, 0, s1>>>();
    k_scan3<<<NSCAN_BLK, 1024, 0, s1>>>();
    k_scatter<<<NB_E, 256, 0, s1>>>(src, dst);
    cudaEventRecord(evGraph, s1);

    cudaStreamWaitEvent(0, evW, 0);

    // layer 0: column-split GEMM; SpMM chunk0 overlapped on s2
    k_gemm_tc<1><<<ghalf, 256, SMEM_G>>>(bufB, w0, nullptr, ns,
                                         nullptr, z16, nullptr, N_NODES, 0);
    cudaEventRecord(evA0, 0);
    k_gemm_tc<1><<<ghalf, 256, SMEM_G>>>(bufB, w0, nullptr, ns,
                                         nullptr, z16, nullptr, N_NODES, 2);
    cudaStreamWaitEvent(0, evGraph, 0);
    cudaStreamWaitEvent(s2, evGraph, 0);
    cudaStreamWaitEvent(s2, evA0, 0);
    k_spmm16<<<spmm_blocks, 128, 0, s2>>>(z16, b0, bufA, 0);
    cudaEventRecord(evC0, s2);
    k_spmm16<<<spmm_blocks, 128>>>(z16, b0, bufA, 1);
    cudaStreamWaitEvent(0, evC0, 0);

    // layer 1
    k_gemm_tc<1><<<ghalf, 256, SMEM_G>>>(bufA, w1, nullptr, ns,
                                         nullptr, z16, nullptr, N_NODES, 0);
    cudaEventRecord(evA1, 0);
    k_gemm_tc<1><<<ghalf, 256, SMEM_G>>>(bufA, w1, nullptr, ns,
                                         nullptr, z16, nullptr, N_NODES, 2);
    cudaStreamWaitEvent(s2, evA1, 0);
    k_spmm16<<<spmm_blocks, 128, 0, s2>>>(z16, b1, bufB, 0);
    cudaEventRecord(evC1, s2);
    k_spmm16<<<spmm_blocks, 128>>>(z16, b1, bufB, 1);
    cudaStreamWaitEvent(0, evC1, 0);

    // layer 2
    k_gemm_tc<2><<<g40, 256, SMEM_G>>>(bufB, w2, nullptr, ns,
                                       nullptr, nullptr, z40, N_NODES, 0);
    k_spmm40<<<(N_NODES + 7) / 8, 256>>>(z40, b2, out);
}

// round 16
// speedup vs baseline: 1.2005x; 1.0054x over previous
#include <cuda_runtime.h>
#include <cuda_bf16.h>
#include <cuda_fp16.h>
#include <math.h>
#include <stdint.h>

#define N_NODES   100000
#define N_EDGES   3200000
#define D         512
#define N_CLASSES 40
#define NSCAN_BLK 98
#define ROWS_HALF 50048              // 391 * 128

// ---------------- scratch (device globals; no allocs allowed) ----------------
__device__ __half g_bufA[(size_t)N_NODES * D];  // node features fp16, canonical layout
__device__ __half g_bufB[(size_t)N_NODES * D];
__device__ __half g_z16[(size_t)N_NODES * D];   // GEMM out / SpMM in, canonical
__device__ __half g_z40[(size_t)N_NODES * N_CLASSES];
__device__ __half g_wl[D * D];                   // W^T [n][k] fp16 canonical
__device__ __half g_w0[D * D];
__device__ __half g_w1[D * D];
__device__ __half g_w2[64 * D];                  // W2^T [n][k], padded to 64 rows
__device__ int   g_indeg[N_NODES];
__device__ int   g_outdeg[N_NODES];
__device__ float g_norm_src[N_NODES];
__device__ float g_norm_dst[N_NODES];
__device__ int   g_rowptr[N_NODES + 1];
__device__ int   g_rowctr[N_NODES];
__device__ int   g_csr_src[N_EDGES];
__device__ int   g_blksum[NSCAN_BLK];
__device__ int   g_blkoff[NSCAN_BLK];

// ---------------- helpers ----------------
__device__ __forceinline__ void cp16(uint32_t dst_smem, const void* src, bool valid) {
    asm volatile("cp.async.cg.shared.global [%0], [%1], 16, %2;"
                 :: "r"(dst_smem), "l"(src), "r"(valid ? 16 : 0));
}
__device__ __forceinline__ void cp_commit() {
    asm volatile("cp.async.commit_group;");
}
template <int N>
__device__ __forceinline__ void cp_wait() {
    asm volatile("cp.async.wait_group %0;" :: "n"(N));
}

#define LDM4(r, addr)                                                          \
    asm volatile("ldmatrix.sync.aligned.m8n8.x4.shared.b16 {%0,%1,%2,%3}, [%4];" \
                 : "=r"((r)[0]), "=r"((r)[1]), "=r"((r)[2]), "=r"((r)[3])      \
                 : "r"(addr))

#define MMA_F16(c, a0, a1, a2, a3, b0, b1)                                     \
    asm volatile("mma.sync.aligned.m16n8k16.row.col.f32.f16.f16.f32 "          \
                 "{%0,%1,%2,%3}, {%4,%5,%6,%7}, {%8,%9}, {%0,%1,%2,%3};"       \
                 : "+f"(c[0]), "+f"(c[1]), "+f"(c[2]), "+f"(c[3])              \
                 : "r"(a0), "r"(a1), "r"(a2), "r"(a3), "r"(b0), "r"(b1))

// ---------------- conversion passes (canonical layouts) ----------------
// converts 8 elems/thread starting at float index base*D
__global__ void k_conv_feat(const float* __restrict__ f, size_t base_elem) {
    size_t i = base_elem + ((size_t)blockIdx.x * blockDim.x + threadIdx.x) * 8;
    float4 a = *(const float4*)(f + i);
    float4 b = *(const float4*)(f + i + 4);
    __half2 h0 = __floats2half2_rn(a.x, a.y);
    __half2 h1 = __floats2half2_rn(a.z, a.w);
    __half2 h2 = __floats2half2_rn(b.x, b.y);
    __half2 h3 = __floats2half2_rn(b.z, b.w);
    *(uint4*)(g_bufA + i) = make_uint4(*(uint32_t*)&h0, *(uint32_t*)&h1,
                                       *(uint32_t*)&h2, *(uint32_t*)&h3);
}

// W [k][n] fp32 -> W^T [n][k] fp16
__global__ void k_conv_w(const float* __restrict__ W, __half* __restrict__ Wt) {
    int idx = blockIdx.x * blockDim.x + threadIdx.x;
    int k = idx >> 9, n = idx & 511;
    Wt[n * 512 + k] = __float2half(W[k * 512 + n]);
}

// W2 [k][40] -> padded [n][k], n 0..63
__global__ void k_conv_w2(const float* __restrict__ W2) {
    int idx = blockIdx.x * blockDim.x + threadIdx.x;   // 64*512
    int n = idx >> 9, k = idx & 511;
    float v = (n < N_CLASSES) ? W2[k * N_CLASSES + n] : 0.f;
    g_w2[n * 512 + k] = __float2half(v);
}

// ---------------- graph preprocessing ----------------
__global__ void k_zero_ints() {
    int i = blockIdx.x * blockDim.x + threadIdx.x;
    if (i < N_NODES) { g_indeg[i] = 0; g_outdeg[i] = 0; g_rowctr[i] = 0; }
}

__global__ void k_degrees(const int* __restrict__ src, const int* __restrict__ dst) {
    int e = blockIdx.x * blockDim.x + threadIdx.x;
    if (e < N_EDGES) {
        atomicAdd(&g_outdeg[src[e]], 1);
        atomicAdd(&g_indeg[dst[e]], 1);
    }
}

__global__ void k_norms() {
    int i = blockIdx.x * blockDim.x + threadIdx.x;
    if (i < N_NODES) {
        g_norm_src[i] = rsqrtf(fmaxf((float)g_outdeg[i], 1.0f));
        g_norm_dst[i] = rsqrtf(fmaxf((float)g_indeg[i], 1.0f));
    }
}

__global__ void k_scan1() {
    __shared__ int ws[32];
    int tid = threadIdx.x, lane = tid & 31, w = tid >> 5;
    int i = blockIdx.x * 1024 + tid;
    int v = (i < N_NODES) ? g_indeg[i] : 0;
    int x = v;
    #pragma unroll
    for (int o = 1; o < 32; o <<= 1) {
        int y = __shfl_up_sync(0xFFFFFFFFu, x, o);
        if (lane >= o) x += y;
    }
    if (lane == 31) ws[w] = x;
    __syncthreads();
    if (w == 0) {
        int y = ws[lane];
        #pragma unroll
        for (int o = 1; o < 32; o <<= 1) {
            int z = __shfl_up_sync(0xFFFFFFFFu, y, o);
            if (lane >= o) y += z;
        }
        ws[lane] = y;
    }
    __syncthreads();
    int incl = x + (w > 0 ? ws[w - 1] : 0);
    if (i < N_NODES) g_rowptr[i + 1] = incl;
    if (tid == 1023) g_blksum[blockIdx.x] = incl;
}

__global__ void k_scan2() {
    __shared__ int ws[4];
    int tid = threadIdx.x, lane = tid & 31, w = tid >> 5;
    int v = (tid < NSCAN_BLK) ? g_blksum[tid] : 0;
    int x = v;
    #pragma unroll
    for (int o = 1; o < 32; o <<= 1) {
        int y = __shfl_up_sync(0xFFFFFFFFu, x, o);
        if (lane >= o) x += y;
    }
    if (lane == 31) ws[w] = x;
    __syncthreads();
    if (tid == 0) {
        int s = 0;
        #pragma unroll
        for (int j = 0; j < 4; j++) { int t = ws[j]; ws[j] = s; s += t; }
    }
    __syncthreads();
    int excl = x - v + ws[w];
    if (tid < NSCAN_BLK) g_blkoff[tid] = excl;
}

__global__ void k_scan3() {
    int i = blockIdx.x * 1024 + threadIdx.x;
    if (i < N_NODES) g_rowptr[i + 1] += g_blkoff[blockIdx.x];
    if (i == 0) g_rowptr[0] = 0;
}

__global__ void k_scatter(const int* __restrict__ src, const int* __restrict__ dst) {
    int e = blockIdx.x * blockDim.x + threadIdx.x;
    if (e < N_EDGES) {
        int d = dst[e];
        int pos = g_rowptr[d] + atomicAdd(&g_rowctr[d], 1);
        g_csr_src[pos] = src[e];
    }
}

// ---------------- fp16 tensor-core GEMM (ldmatrix; 3 stages, 2 barriers) ----------------
// MODE 0: C = acc + bias     -> fp16 Ch
// MODE 1: C = acc * scale[r] -> fp16 C16
// MODE 2: C = acc * scale[r] -> fp16 C40, row stride 40, cols < 40 only
// TN = N tile width (128 for big GEMMs, 64 for the 40-class GEMM).
#define ROWB   80
#define APARTB (128 * ROWB)                  // 10240

template <int MODE, int TN>
__global__ __launch_bounds__(256, 2) void k_gemm_tc(
        const __half* __restrict__ A, const __half* __restrict__ B,
        const float* __restrict__ bias, const float* __restrict__ row_scale,
        __half* __restrict__ Ch, __half* __restrict__ C16,
        __half* __restrict__ C40, int M, int col_base, int row_base) {
    constexpr int BPARTB = TN * ROWB;
    constexpr int STGB   = APARTB + BPARTB;
    constexpr int NTP    = TN / 32;          // B LDM4s per sub per warp
    extern __shared__ char smc[];
    uint32_t sbase = (uint32_t)__cvta_generic_to_shared(smc);

    int tid  = threadIdx.x;
    int lane = tid & 31;
    int warp = tid >> 5;
    int wm = (warp & 3) * 32;
    int wn = (warp >> 2) * (TN / 2);
    int row0 = (blockIdx.y + row_base) * 128;
    int col0 = (blockIdx.x + col_base) * TN;

    float acc[2][2 * NTP][4];
    #pragma unroll
    for (int i = 0; i < 2; i++)
        #pragma unroll
        for (int j = 0; j < 2 * NTP; j++)
            #pragma unroll
            for (int k = 0; k < 4; k++) acc[i][j][k] = 0.f;

    // cp.async: thread -> row (tid>>1), 16-half half-row (tid&1)
    const int r_ld = tid >> 1;
    const int half = tid & 1;
    const bool a_ok = (row0 + r_ld) < M;
    const bool b_ld = r_ld < TN;
    const size_t a_off = (size_t)(row0 + r_ld) * D + half * 16;   // halves
    const size_t b_off = (size_t)(col0 + r_ld) * D + half * 16;
    const uint32_t dstA = (uint32_t)r_ld * ROWB + half * 32;      // bytes

    auto issue = [&](int st, int ks) {
        int k0 = ks * 32;
        uint32_t sb = sbase + st * STGB;
        const char* pa = (const char*)(A + a_off + k0);
        cp16(sb + dstA,      pa,      a_ok);
        cp16(sb + dstA + 16, pa + 16, a_ok);
        if (b_ld) {
            const char* pb = (const char*)(B + b_off + k0);
            cp16(sb + APARTB + dstA,      pb,      true);
            cp16(sb + APARTB + dstA + 16, pb + 16, true);
        }
        cp_commit();
    };

    issue(0, 0);
    issue(1, 1);

    // ldmatrix per-lane address offsets (relative to stage base, bytes)
    const uint32_t a_lane = (uint32_t)(wm + (lane & 7) + ((lane >> 3) & 1) * 8) * ROWB
                          + ((lane >> 4) & 1) * 16;
    const uint32_t b_lane = APARTB
                          + (uint32_t)(wn + (lane & 7) + ((lane >> 4) & 1) * 8) * ROWB
                          + ((lane >> 3) & 1) * 16;

    const int NK = D / 32;   // 16
    for (int ks = 0; ks < NK; ks++) {
        if (ks < NK - 1) cp_wait<1>(); else cp_wait<0>();
        __syncthreads();
        if (ks + 2 < NK) issue((ks + 2) % 3, ks + 2);

        uint32_t sb = sbase + (ks % 3) * STGB;
        #pragma unroll
        for (int sub = 0; sub < 2; sub++) {
            uint32_t a0[4], a1[4];
            LDM4(a0, sb + a_lane + sub * 32);
            LDM4(a1, sb + a_lane + 16 * ROWB + sub * 32);
            #pragma unroll
            for (int ntp = 0; ntp < NTP; ntp++) {
                uint32_t bq[4];
                LDM4(bq, sb + b_lane + ntp * 16 * ROWB + sub * 32);
                MMA_F16(acc[0][2 * ntp],     a0[0], a0[1], a0[2], a0[3], bq[0], bq[1]);
                MMA_F16(acc[1][2 * ntp],     a1[0], a1[1], a1[2], a1[3], bq[0], bq[1]);
                MMA_F16(acc[0][2 * ntp + 1], a0[0], a0[1], a0[2], a0[3], bq[2], bq[3]);
                MMA_F16(acc[1][2 * ntp + 1], a1[0], a1[1], a1[2], a1[3], bq[2], bq[3]);
            }
        }
        __syncthreads();
    }

    int fr = lane >> 2;
    int fc = (lane & 3) * 2;
    #pragma unroll
    for (int mt = 0; mt < 2; mt++) {
        int r = row0 + wm + mt * 16 + fr;
        float s0 = 1.f, s1 = 1.f;
        if (MODE != 0) {
            if (r < M)     s0 = row_scale[r];
            if (r + 8 < M) s1 = row_scale[r + 8];
        }
        #pragma unroll
        for (int nt = 0; nt < 2 * NTP; nt++) {
            int cb = col0 + wn + nt * 8 + fc;
            float v0 = acc[mt][nt][0], v1 = acc[mt][nt][1];
            float v2 = acc[mt][nt][2], v3 = acc[mt][nt][3];
            if (MODE == 0) {
                float bb0 = bias[cb], bb1 = bias[cb + 1];
                __half2 h01 = __floats2half2_rn(v0 + bb0, v1 + bb1);
                __half2 h23 = __floats2half2_rn(v2 + bb0, v3 + bb1);
                if (r < M)     *(__half2*)(Ch + (size_t)r * D + cb)       = h01;
                if (r + 8 < M) *(__half2*)(Ch + (size_t)(r + 8) * D + cb) = h23;
            } else if (MODE == 1) {
                if (r < M)
                    *(__half2*)(C16 + (size_t)r * D + cb) = __floats2half2_rn(v0 * s0, v1 * s0);
                if (r + 8 < M)
                    *(__half2*)(C16 + (size_t)(r + 8) * D + cb) = __floats2half2_rn(v2 * s1, v3 * s1);
            } else {
                if (cb < N_CLASSES) {
                    if (r < M)
                        *(__half2*)(C40 + (size_t)r * N_CLASSES + cb) = __floats2half2_rn(v0 * s0, v1 * s0);
                    if (r + 8 < M)
                        *(__half2*)(C40 + (size_t)(r + 8) * N_CLASSES + cb) = __floats2half2_rn(v2 * s1, v3 * s1);
                }
            }
        }
    }
}

#define SMEM_G128 (3 * (APARTB + 128 * ROWB))   // 61440
#define SMEM_G64  (3 * (APARTB + 64 * ROWB))    // 46080

// ---------------- SpMM: fp16 gather, 2 x 256-col chunks; writes fp16 h ----------------
__global__ __launch_bounds__(128) void k_spmm16(const __half* __restrict__ z,
                                                const float* __restrict__ bias,
                                                __half* __restrict__ O,
                                                int chunk) {
    int v = blockIdx.x * 4 + (threadIdx.x >> 5);
    if (v >= N_NODES) return;
    int lane = threadIdx.x & 31;
    int coff = chunk * 256 + lane * 8;

    int beg = g_rowptr[v], end = g_rowptr[v + 1];
    float acc[8];
    #pragma unroll
    for (int j = 0; j < 8; j++) acc[j] = 0.f;

    int e = beg;
    for (; e + 3 < end; e += 4) {
        int u0 = g_csr_src[e];
        int u1 = g_csr_src[e + 1];
        int u2 = g_csr_src[e + 2];
        int u3 = g_csr_src[e + 3];
        uint4 q0 = *(const uint4*)(z + (size_t)u0 * D + coff);
        uint4 q1 = *(const uint4*)(z + (size_t)u1 * D + coff);
        uint4 q2 = *(const uint4*)(z + (size_t)u2 * D + coff);
        uint4 q3 = *(const uint4*)(z + (size_t)u3 * D + coff);
        const __half2* p0 = (const __half2*)&q0;
        const __half2* p1 = (const __half2*)&q1;
        const __half2* p2 = (const __half2*)&q2;
        const __half2* p3 = (const __half2*)&q3;
        #pragma unroll
        for (int p = 0; p < 4; p++) {
            float2 f0 = __half22float2(p0[p]);
            float2 f1 = __half22float2(p1[p]);
            float2 f2 = __half22float2(p2[p]);
            float2 f3 = __half22float2(p3[p]);
            acc[2 * p]     += (f0.x + f1.x) + (f2.x + f3.x);
            acc[2 * p + 1] += (f0.y + f1.y) + (f2.y + f3.y);
        }
    }
    for (; e < end; e++) {
        int u0 = g_csr_src[e];
        uint4 q0 = *(const uint4*)(z + (size_t)u0 * D + coff);
        const __half2* p0 = (const __half2*)&q0;
        #pragma unroll
        for (int p = 0; p < 4; p++) {
            float2 f0 = __half22float2(p0[p]);
            acc[2 * p]     += f0.x;
            acc[2 * p + 1] += f0.y;
        }
    }

    float nd = g_norm_dst[v];
    float4 b0v = *(const float4*)(bias + coff);
    float4 b1v = *(const float4*)(bias + coff + 4);
    float bb[8] = { b0v.x, b0v.y, b0v.z, b0v.w, b1v.x, b1v.y, b1v.z, b1v.w };
    __half2 oh[4];
    #pragma unroll
    for (int p = 0; p < 4; p++) {
        float x = fmaxf(fmaf(acc[2 * p],     nd, bb[2 * p]),     0.f);
        float y = fmaxf(fmaf(acc[2 * p + 1], nd, bb[2 * p + 1]), 0.f);
        oh[p] = __floats2half2_rn(x, y);
    }
    *(uint4*)(O + (size_t)v * D + coff) =
        make_uint4(*(uint32_t*)&oh[0], *(uint32_t*)&oh[1],
                   *(uint32_t*)&oh[2], *(uint32_t*)&oh[3]);
}

// ---------------- final SpMM on 40-wide fp16 z40 (L2-resident) ----------------
__global__ __launch_bounds__(256) void k_spmm40(const __half* __restrict__ z40,
                                                const float* __restrict__ bias,
                                                float* __restrict__ out) {
    int v = blockIdx.x * 8 + (threadIdx.x >> 5);
    if (v >= N_NODES) return;
    int lane = threadIdx.x & 31;
    if (lane >= 20) return;
    int c = lane * 2;

    int beg = g_rowptr[v], end = g_rowptr[v + 1];
    float2 acc0 = make_float2(0.f, 0.f);
    float2 acc1 = make_float2(0.f, 0.f);
    int e = beg;
    for (; e + 1 < end; e += 2) {
        int u0 = g_csr_src[e];
        int u1 = g_csr_src[e + 1];
        __half2 x0 = *(const __half2*)(z40 + (size_t)u0 * N_CLASSES + c);
        __half2 x1 = *(const __half2*)(z40 + (size_t)u1 * N_CLASSES + c);
        float2 f0 = __half22float2(x0);
        float2 f1 = __half22float2(x1);
        acc0.x += f0.x; acc0.y += f0.y;
        acc1.x += f1.x; acc1.y += f1.y;
    }
    if (e < end) {
        int u0 = g_csr_src[e];
        __half2 x0 = *(const __half2*)(z40 + (size_t)u0 * N_CLASSES + c);
        float2 f0 = __half22float2(x0);
        acc0.x += f0.x; acc0.y += f0.y;
    }
    float nd = g_norm_dst[v];
    float2 o;
    o.x = fmaf(acc0.x + acc1.x, nd, bias[c]);
    o.y = fmaf(acc0.y + acc1.y, nd, bias[c + 1]);
    *(float2*)(out + (size_t)v * N_CLASSES + c) = o;
}

// ---------------- launch ----------------
extern "C" void kernel_launch(void* const* d_in, const int* in_sizes, int n_in,
                              void* d_out, int out_size) {
    const float* features = (const float*)d_in[0];
    const int*   src      = (const int*)d_in[1];
    const int*   dst      = (const int*)d_in[2];
    const float* W_lin    = (const float*)d_in[3];
    const float* b_lin    = (const float*)d_in[4];
    const float* W0       = (const float*)d_in[5];
    const float* b0       = (const float*)d_in[6];
    const float* W1       = (const float*)d_in[7];
    const float* b1       = (const float*)d_in[8];
    const float* W2       = (const float*)d_in[9];
    const float* b2       = (const float*)d_in[10];
    float* out = (float*)d_out;

    static cudaStream_t s1 = nullptr, s2 = nullptr;
    static cudaEvent_t evFork, evFB, evW, evGraph, evA0, evC0, evA1, evC1;
    if (s1 == nullptr) {
        cudaStreamCreateWithFlags(&s1, cudaStreamNonBlocking);
        cudaStreamCreateWithFlags(&s2, cudaStreamNonBlocking);
        cudaEventCreateWithFlags(&evFork,  cudaEventDisableTiming);
        cudaEventCreateWithFlags(&evFB,    cudaEventDisableTiming);
        cudaEventCreateWithFlags(&evW,     cudaEventDisableTiming);
        cudaEventCreateWithFlags(&evGraph, cudaEventDisableTiming);
        cudaEventCreateWithFlags(&evA0,    cudaEventDisableTiming);
        cudaEventCreateWithFlags(&evC0,    cudaEventDisableTiming);
        cudaEventCreateWithFlags(&evA1,    cudaEventDisableTiming);
        cudaEventCreateWithFlags(&evC1,    cudaEventDisableTiming);
        cudaFuncSetAttribute(k_gemm_tc<0,128>, cudaFuncAttributeMaxDynamicSharedMemorySize, SMEM_G128);
        cudaFuncSetAttribute(k_gemm_tc<1,128>, cudaFuncAttributeMaxDynamicSharedMemorySize, SMEM_G128);
        cudaFuncSetAttribute(k_gemm_tc<2,64>,  cudaFuncAttributeMaxDynamicSharedMemorySize, SMEM_G64);
    }

    __half *bufA, *bufB, *wl, *w0, *w1, *w2, *z16, *z40;
    float *ns;
    cudaGetSymbolAddress((void**)&bufA, g_bufA);
    cudaGetSymbolAddress((void**)&bufB, g_bufB);
    cudaGetSymbolAddress((void**)&wl, g_wl);
    cudaGetSymbolAddress((void**)&w0, g_w0);
    cudaGetSymbolAddress((void**)&w1, g_w1);
    cudaGetSymbolAddress((void**)&w2, g_w2);
    cudaGetSymbolAddress((void**)&z16, g_z16);
    cudaGetSymbolAddress((void**)&z40, g_z40);
    cudaGetSymbolAddress((void**)&ns, g_norm_src);

    const int NB_N = (N_NODES + 255) / 256;
    const int NB_E = (N_EDGES + 255) / 256;
    dim3 gfullH(4, 391);                    // row-half grid (391*128 = 50048 rows)
    dim3 ghalf(2, (N_NODES + 127) / 128);
    dim3 g40(1, (N_NODES + 127) / 128);
    const int spmm_blocks = (N_NODES + 3) / 4;
    const size_t elemsA = (size_t)ROWS_HALF * D;            // 25,624,576
    const int fa_blocks = (int)(elemsA / 8 / 256);          // 12512
    const int fb_blocks = (int)(((size_t)(N_NODES - ROWS_HALF) * D) / 8 / 256); // 12488

    cudaEventRecord(evFork, 0);
    cudaStreamWaitEvent(s1, evFork, 0);
    cudaStreamWaitEvent(s2, evFork, 0);

    // second feature half on s2, concurrent with GEMM0a
    k_conv_feat<<<fb_blocks, 256, 0, s2>>>(features, elemsA);
    cudaEventRecord(evFB, s2);

    // main stream: wl + first feature half + GEMM0a (launch idx 3 on main for ncu)
    k_conv_w<<<1024, 256>>>(W_lin, wl);                                        // 0
    k_conv_feat<<<fa_blocks, 256>>>(features, 0);                              // 1
    k_conv_w<<<1024, 256, 0, s1>>>(W0, w0);                                    // 2 (s1)
    k_gemm_tc<0,128><<<gfullH, 256, SMEM_G128>>>(bufA, wl, b_lin, nullptr,     // 3 <- profiled
                                                 bufB, nullptr, nullptr, N_NODES, 0, 0);
    cudaStreamWaitEvent(0, evFB, 0);
    k_gemm_tc<0,128><<<gfullH, 256, SMEM_G128>>>(bufA, wl, b_lin, nullptr,
                                                 bufB, nullptr, nullptr, N_NODES, 0, 391);

    // side stream: remaining weights + graph build; evW AFTER norms
    k_conv_w<<<1024, 256, 0, s1>>>(W1, w1);
    k_conv_w2<<<128, 256, 0, s1>>>(W2);
    k_zero_ints<<<NB_N, 256, 0, s1>>>();
    k_degrees<<<NB_E, 256, 0, s1>>>(src, dst);
    k_norms<<<NB_N, 256, 0, s1>>>();
    cudaEventRecord(evW, s1);
    k_scan1<<<NSCAN_BLK, 1024, 0, s1>>>();
    k_scan2<<<1, 128, 0, s1>>>();
    k_scan3<<<NSCAN_BLK, 1024, 0, s1>>>();
    k_scatter<<<NB_E, 256, 0, s1>>>(src, dst);
    cudaEventRecord(evGraph, s1);

    cudaStreamWaitEvent(0, evW, 0);

    // layer 0: column-split GEMM; SpMM chunk0 overlapped on s2
    k_gemm_tc<1,128><<<ghalf, 256, SMEM_G128>>>(bufB, w0, nullptr, ns,
                                                nullptr, z16, nullptr, N_NODES, 0, 0);
    cudaEventRecord(evA0, 0);
    k_gemm_tc<1,128><<<ghalf, 256, SMEM_G128>>>(bufB, w0, nullptr, ns,
                                                nullptr, z16, nullptr, N_NODES, 2, 0);
    cudaStreamWaitEvent(0, evGraph, 0);
    cudaStreamWaitEvent(s2, evGraph, 0);
    cudaStreamWaitEvent(s2, evA0, 0);
    k_spmm16<<<spmm_blocks, 128, 0, s2>>>(z16, b0, bufA, 0);
    cudaEventRecord(evC0, s2);
    k_spmm16<<<spmm_blocks, 128>>>(z16, b0, bufA, 1);
    cudaStreamWaitEvent(0, evC0, 0);

    // layer 1
    k_gemm_tc<1,128><<<ghalf, 256, SMEM_G128>>>(bufA, w1, nullptr, ns,
                                                nullptr, z16, nullptr, N_NODES, 0, 0);
    cudaEventRecord(evA1, 0);
    k_gemm_tc<1,128><<<ghalf, 256, SMEM_G128>>>(bufA, w1, nullptr, ns,
                                                nullptr, z16, nullptr, N_NODES, 2, 0);
    cudaStreamWaitEvent(s2, evA1, 0);
    k_spmm16<<<spmm_blocks, 128, 0, s2>>>(z16, b1, bufB, 0);
    cudaEventRecord(evC1, s2);
    k_spmm16<<<spmm_blocks, 128>>>(z16, b1, bufB, 1);
    cudaStreamWaitEvent(0, evC1, 0);

    // layer 2 (TN=64 tile: half the MMAs of a 128-wide tile)
    k_gemm_tc<2,64><<<g40, 256, SMEM_G64>>>(bufB, w2, nullptr, ns,
                                            nullptr, nullptr, z40, N_NODES, 0, 0);
    k_spmm40<<<(N_NODES + 7) / 8, 256>>>(z40, b2, out);
}